// round 11
// baseline (speedup 1.0000x reference)
#include <cuda_runtime.h>
#include <cuda_fp16.h>
#include <cstdint>

// Problem constants (fixed by setup_inputs)
#define BATCH 4
#define SEQ   2048
#define CDIM  768
#define NHEAD 12
#define HD    64
#define MROWS (BATCH*SEQ)      // 8192
#define C3    (3*CDIM)         // 2304
#define LOG2E 1.4426950408889634f

// Scratch (device globals; no runtime allocation)
__device__ __half g_qkhi[(size_t)MROWS * C3];
__device__ __half g_qklo[(size_t)MROWS * C3];    // only Q section written/read
__device__ __half g_xhi[(size_t)MROWS * CDIM];
__device__ __half g_xlo[(size_t)MROWS * CDIM];
__device__ __half g_wahi[(size_t)CDIM * C3];     // weights: hi only (split-2)
__device__ __half g_wphi[(size_t)CDIM * CDIM];
__device__ __half g_yhi[(size_t)MROWS * CDIM];
__device__ __half g_ylo[(size_t)MROWS * CDIM];

__device__ __forceinline__ float ex2(float x) {
    float y;
    asm("ex2.approx.f32 %0, %1;" : "=f"(y) : "f"(x));
    return y;
}
__device__ __forceinline__ uint32_t smem_u32(const void* p) {
    return (uint32_t)__cvta_generic_to_shared(p);
}
__device__ __forceinline__ void cp16(uint32_t dst, const void* src) {
    asm volatile("cp.async.ca.shared.global [%0], [%1], 16;\n" :: "r"(dst), "l"(src));
}
__device__ __forceinline__ void cp_commit() {
    asm volatile("cp.async.commit_group;\n" ::: "memory");
}
__device__ __forceinline__ void cp_wait0() {
    asm volatile("cp.async.wait_group 0;\n" ::: "memory");
}
__device__ __forceinline__ void cp_wait1() {
    asm volatile("cp.async.wait_group 1;\n" ::: "memory");
}
__device__ __forceinline__ void ldsm_x4(uint32_t& r0, uint32_t& r1, uint32_t& r2, uint32_t& r3,
                                        uint32_t addr) {
    asm volatile("ldmatrix.sync.aligned.m8n8.x4.shared.b16 {%0,%1,%2,%3}, [%4];"
                 : "=r"(r0), "=r"(r1), "=r"(r2), "=r"(r3) : "r"(addr));
}
__device__ __forceinline__ void ldsm_x4t(uint32_t& r0, uint32_t& r1, uint32_t& r2, uint32_t& r3,
                                         uint32_t addr) {
    asm volatile("ldmatrix.sync.aligned.m8n8.x4.trans.shared.b16 {%0,%1,%2,%3}, [%4];"
                 : "=r"(r0), "=r"(r1), "=r"(r2), "=r"(r3) : "r"(addr));
}
__device__ __forceinline__ void ldsm_x2t(uint32_t& r0, uint32_t& r1, uint32_t addr) {
    asm volatile("ldmatrix.sync.aligned.m8n8.x2.trans.shared.b16 {%0,%1}, [%2];"
                 : "=r"(r0), "=r"(r1) : "r"(addr));
}
__device__ __forceinline__ void mma16816(float* c,
                                         uint32_t a0, uint32_t a1, uint32_t a2, uint32_t a3,
                                         uint32_t b0, uint32_t b1) {
    asm volatile("mma.sync.aligned.m16n8k16.row.col.f32.f16.f16.f32 "
                 "{%0,%1,%2,%3}, {%4,%5,%6,%7}, {%8,%9}, {%0,%1,%2,%3};"
                 : "+f"(c[0]), "+f"(c[1]), "+f"(c[2]), "+f"(c[3])
                 : "r"(a0), "r"(a1), "r"(a2), "r"(a3), "r"(b0), "r"(b1));
}
__device__ __forceinline__ uint32_t pack2(float a, float b) {
    __half2 h = __halves2half2(__float2half_rn(a), __float2half_rn(b));
    return *reinterpret_cast<uint32_t*>(&h);
}

// ---------------------------------------------------------------------------
// fp32 -> (fp16 hi, fp16 lo) split, vectorized by 4. (A operands)
// ---------------------------------------------------------------------------
__global__ void __launch_bounds__(256) split_fp32(
    const float4* __restrict__ src, __half2* __restrict__ hi,
    __half2* __restrict__ lo, int n4)
{
    const int i = blockIdx.x * blockDim.x + threadIdx.x;
    if (i >= n4) return;
    float4 v = src[i];
    __half h0 = __float2half_rn(v.x), h1 = __float2half_rn(v.y);
    __half h2 = __float2half_rn(v.z), h3 = __float2half_rn(v.w);
    hi[2*i]   = __halves2half2(h0, h1);
    hi[2*i+1] = __halves2half2(h2, h3);
    lo[2*i]   = __halves2half2(__float2half_rn(v.x - __half2float(h0)),
                               __float2half_rn(v.y - __half2float(h1)));
    lo[2*i+1] = __halves2half2(__float2half_rn(v.z - __half2float(h2)),
                               __float2half_rn(v.w - __half2float(h3)));
}

// fp32 -> fp16 convert only (B operands: hi part only)
__global__ void __launch_bounds__(256) cvt_fp16(
    const float4* __restrict__ src, __half2* __restrict__ hi, int n4)
{
    const int i = blockIdx.x * blockDim.x + threadIdx.x;
    if (i >= n4) return;
    float4 v = src[i];
    hi[2*i]   = __halves2half2(__float2half_rn(v.x), __float2half_rn(v.y));
    hi[2*i+1] = __halves2half2(__float2half_rn(v.z), __float2half_rn(v.w));
}

// ---------------------------------------------------------------------------
// Split-2 fp16 tensor-core GEMM + bias, cp.async 3-stage pipeline, BK=32.
//   C = (Ahi+Alo) @ Bhi + bias
// R7-proven ordering (prefetch at top, wait+sync at bottom) + third stage.
// OUT_HALF: write hi/lo fp16 (lo only for Q columns c<CDIM). Else fp32.
// BM=128, BK=32, 256 threads = 8 warps (2x4 grid, 64x32 per warp).
// ---------------------------------------------------------------------------
#define BK    32
#define A_STR 40
#define B_STR 136
#define HG_ABUF (128 * A_STR)
#define HG_BBUF (BK * B_STR)
#define HG_STAGE (2 * HG_ABUF + HG_BBUF)         // halves (14592)
#define HG_SMEM  (3 * HG_STAGE * 2)              // bytes (~87.5 KB)

template<bool OUT_HALF>
__global__ void __launch_bounds__(256, 2) hgemm_split(
    const __half* __restrict__ Ahi, const __half* __restrict__ Alo,
    const __half* __restrict__ Bhi,
    const float* __restrict__ bias, float* __restrict__ C,
    __half* __restrict__ Chi, __half* __restrict__ Clo,
    int N, int K)
{
    extern __shared__ __align__(16) __half hsm[];

    const int t    = threadIdx.x;
    const int warp = t >> 5;
    const int lane = t & 31;
    const int wm   = (warp & 1) * 64;
    const int wn   = (warp >> 1) * 32;

    const size_t aG   = (size_t)blockIdx.y * 128 * K;
    const int    bCol = blockIdx.x * 128;

    const int g     = lane >> 3;
    const int lr    = lane & 7;
    const int aRowF = (g & 1) * 8 + lr;
    const int aColF = (g >> 1) * 8;
    const int bRowF = ((lane >> 3) & 1) * 8 + lr;

    float acc[4][4][4];
    #pragma unroll
    for (int mt = 0; mt < 4; mt++)
        #pragma unroll
        for (int nt = 0; nt < 4; nt++)
            #pragma unroll
            for (int i = 0; i < 4; i++) acc[mt][nt][i] = 0.0f;

    auto load_tile = [&](int s, int ko) {
        __half* base = hsm + s * HG_STAGE;
        __half* aH = base;
        __half* aL = base + HG_ABUF;
        __half* bH = base + 2 * HG_ABUF;
        #pragma unroll
        for (int it = 0; it < 2; it++) {
            const int u   = it * 256 + t;
            const int row = u >> 2;
            const int c   = (u & 3) * 8;
            const size_t gsrc = aG + (size_t)row * K + ko + c;
            cp16(smem_u32(aH + row * A_STR + c), Ahi + gsrc);
            cp16(smem_u32(aL + row * A_STR + c), Alo + gsrc);
        }
        #pragma unroll
        for (int it = 0; it < 2; it++) {
            const int u   = it * 256 + t;
            const int row = u >> 4;
            const int c   = (u & 15) * 8;
            cp16(smem_u32(bH + row * B_STR + c), Bhi + (size_t)(ko + row) * N + bCol + c);
        }
        cp_commit();
    };

    const int nk = K / BK;   // 24
    // prologue: stages 0 and 1 in flight
    load_tile(0, 0);
    load_tile(1, BK);
    cp_wait1();              // stage 0 ready (stage 1 may still be in flight)
    __syncthreads();

    for (int kt = 0; kt < nk; kt++) {
        // prefetch kt+2 at top (overwrites stage of kt-1, consumed last iter)
        if (kt + 2 < nk) load_tile((kt + 2) % 3, (kt + 2) * BK);

        const __half* base = hsm + (kt % 3) * HG_STAGE;
        const __half* aH = base;
        const __half* aL = base + HG_ABUF;
        const __half* bH = base + 2 * HG_ABUF;

        #pragma unroll
        for (int ks = 0; ks < 2; ks++) {
            uint32_t afh[4][4], afl[4][4], bfh[4][2];
            #pragma unroll
            for (int mt = 0; mt < 4; mt++) {
                const int row = wm + mt * 16 + aRowF;
                ldsm_x4(afh[mt][0], afh[mt][1], afh[mt][2], afh[mt][3],
                        smem_u32(aH + row * A_STR + ks * 16 + aColF));
                ldsm_x4(afl[mt][0], afl[mt][1], afl[mt][2], afl[mt][3],
                        smem_u32(aL + row * A_STR + ks * 16 + aColF));
            }
            #pragma unroll
            for (int nt = 0; nt < 4; nt++) {
                const int col = wn + nt * 8;
                ldsm_x2t(bfh[nt][0], bfh[nt][1],
                         smem_u32(bH + (ks * 16 + bRowF) * B_STR + col));
            }
            #pragma unroll
            for (int mt = 0; mt < 4; mt++)
                #pragma unroll
                for (int nt = 0; nt < 4; nt++) {
                    mma16816(acc[mt][nt], afh[mt][0], afh[mt][1], afh[mt][2], afh[mt][3],
                             bfh[nt][0], bfh[nt][1]);
                    mma16816(acc[mt][nt], afl[mt][0], afl[mt][1], afl[mt][2], afl[mt][3],
                             bfh[nt][0], bfh[nt][1]);
                }
        }

        if (kt + 1 < nk) {
            // ensure tile kt+1 has landed; keep kt+2's group in flight if issued
            if (kt + 2 < nk) cp_wait1(); else cp_wait0();
            __syncthreads();
        }
    }

    #pragma unroll
    for (int mt = 0; mt < 4; mt++) {
        const int r0 = blockIdx.y * 128 + wm + mt * 16 + (lane >> 2);
        #pragma unroll
        for (int nt = 0; nt < 4; nt++) {
            const int c0 = bCol + wn + nt * 8 + (lane & 3) * 2;
            const float b0 = bias[c0], b1 = bias[c0 + 1];
            const float v00 = acc[mt][nt][0] + b0, v01 = acc[mt][nt][1] + b1;
            const float v10 = acc[mt][nt][2] + b0, v11 = acc[mt][nt][3] + b1;
            if (OUT_HALF) {
                const __half h00 = __float2half_rn(v00), h01 = __float2half_rn(v01);
                const __half h10 = __float2half_rn(v10), h11 = __float2half_rn(v11);
                *(__half2*)(Chi + (size_t)r0 * N + c0)       = __halves2half2(h00, h01);
                *(__half2*)(Chi + (size_t)(r0 + 8) * N + c0) = __halves2half2(h10, h11);
                if (c0 < CDIM) {   // lo only consumed for Q columns
                    *(__half2*)(Clo + (size_t)r0 * N + c0)       = __halves2half2(
                        __float2half_rn(v00 - __half2float(h00)),
                        __float2half_rn(v01 - __half2float(h01)));
                    *(__half2*)(Clo + (size_t)(r0 + 8) * N + c0) = __halves2half2(
                        __float2half_rn(v10 - __half2float(h10)),
                        __float2half_rn(v11 - __half2float(h11)));
                }
            } else {
                *(float2*)(C + (size_t)r0 * N + c0)       = make_float2(v00, v01);
                *(float2*)(C + (size_t)(r0 + 8) * N + c0) = make_float2(v10, v11);
            }
        }
    }
}

// ---------------------------------------------------------------------------
// Tensor-core flash attention, split-2 (unchanged math from R10):
//   S = (Qhi+Qlo)@Khi^T, P = exp2(S*qs - rl*dist), O = (Phi+Plo)@Vhi.
// Occupancy: 3 CTAs/SM (12 warps) for latency hiding.
// ---------------------------------------------------------------------------
#define KV_STR 72
#define AT_BUF (64 * KV_STR)
#define AT_STAGE (2 * AT_BUF)                 // K hi, V hi
#define AT_SMEM ((2 * AT_BUF + 2 * AT_STAGE) * 2)   // bytes (~55 KB)

__global__ void __launch_bounds__(128, 3) attn_mma(
    const __half* __restrict__ qkhi, const __half* __restrict__ qklo,
    const float* __restrict__ decay,
    __half* __restrict__ yhi, __half* __restrict__ ylo)
{
    extern __shared__ __align__(16) __half asm_[];
    __half* QsH = asm_;
    __half* QsL = asm_ + AT_BUF;

    const int q0   = blockIdx.x * 64;
    const int h    = blockIdx.y;
    const int bb   = blockIdx.z;
    const int t    = threadIdx.x;
    const int warp = t >> 5;
    const int lane = t & 31;

    const size_t rowBase = (size_t)bb * SEQ;
    const float r  = decay[h];
    const float rl = r * LOG2E;
    const float qs = 0.125f * LOG2E;

    {
        #pragma unroll
        for (int it = 0; it < 4; it++) {
            const int u = it * 128 + t;
            const int row = u >> 3;
            const int c = (u & 7) * 8;
            const size_t gsrc = (rowBase + q0 + row) * C3 + h * HD + c;
            cp16(smem_u32(QsH + row * KV_STR + c), qkhi + gsrc);
            cp16(smem_u32(QsL + row * KV_STR + c), qklo + gsrc);
        }
        cp_commit();
    }

    auto load_kv = [&](int s, int k0) {
        __half* st = asm_ + 2 * AT_BUF + s * AT_STAGE;
        __half* kH = st;
        __half* vH = st + AT_BUF;
        #pragma unroll
        for (int it = 0; it < 4; it++) {
            const int u = it * 128 + t;
            const int row = u >> 3;
            const int c = (u & 7) * 8;
            const size_t gk = (rowBase + k0 + row) * C3 + CDIM + h * HD + c;
            cp16(smem_u32(kH + row * KV_STR + c), qkhi + gk);
            cp16(smem_u32(vH + row * KV_STR + c), qkhi + gk + CDIM);
        }
        cp_commit();
    };

    const int W = (r > 1e-6f) ? (int)(16.0f / r) : (1 << 30);
    int km = q0 - W;
    if (km < 0) km = 0;
    const int kstart = (km / 64) * 64;

    load_kv(0, kstart);
    cp_wait0();
    __syncthreads();

    const int lr   = lane & 7;
    const int aRow = lr + ((lane >> 3) & 1) * 8;
    const int aCol = (lane >> 4) * 8;
    const int kN   = ((lane >> 4) & 1) * 8;
    const int kK   = ((lane >> 3) & 1) * 8;
    const int vRow = lane & 15;
    const int vN   = (lane >> 4) * 8;

    uint32_t qh[4][4], ql[4][4];
    #pragma unroll
    for (int ks = 0; ks < 4; ks++) {
        ldsm_x4(qh[ks][0], qh[ks][1], qh[ks][2], qh[ks][3],
                smem_u32(QsH + (warp * 16 + aRow) * KV_STR + ks * 16 + aCol));
        ldsm_x4(ql[ks][0], ql[ks][1], ql[ks][2], ql[ks][3],
                smem_u32(QsL + (warp * 16 + aRow) * KV_STR + ks * 16 + aCol));
    }

    float O[8][4];
    #pragma unroll
    for (int nt = 0; nt < 8; nt++)
        #pragma unroll
        for (int i = 0; i < 4; i++) O[nt][i] = 0.0f;
    float lsum0 = 0.0f, lsum1 = 0.0f;

    int buf = 0;
    for (int k0 = kstart; k0 <= q0; k0 += 64) {
        if (k0 != kstart) {
            cp_wait0();
            __syncthreads();
        }
        if (k0 + 64 <= q0) load_kv(buf ^ 1, k0 + 64);

        __half* st = asm_ + 2 * AT_BUF + buf * AT_STAGE;
        const __half* KsH = st;
        const __half* VsH = st + AT_BUF;

        float S[8][4];
        #pragma unroll
        for (int nt = 0; nt < 8; nt++)
            #pragma unroll
            for (int i = 0; i < 4; i++) S[nt][i] = 0.0f;

        #pragma unroll
        for (int ks = 0; ks < 4; ks++) {
            #pragma unroll
            for (int np = 0; np < 4; np++) {
                uint32_t b0, b1, b2, b3;
                ldsm_x4(b0, b1, b2, b3,
                        smem_u32(KsH + (np * 16 + kN + lr) * KV_STR + ks * 16 + kK));
                mma16816(S[2*np],   qh[ks][0], qh[ks][1], qh[ks][2], qh[ks][3], b0, b1);
                mma16816(S[2*np+1], qh[ks][0], qh[ks][1], qh[ks][2], qh[ks][3], b2, b3);
                mma16816(S[2*np],   ql[ks][0], ql[ks][1], ql[ks][2], ql[ks][3], b0, b1);
                mma16816(S[2*np+1], ql[ks][0], ql[ks][1], ql[ks][2], ql[ks][3], b2, b3);
            }
        }

        uint32_t PH0[8], PH1[8], PL0[8], PL1[8];
        const float i0f = (float)(q0 + warp * 16 + (lane >> 2) - k0);
        const float i1f = i0f + 8.0f;
        const float jcb = (float)((lane & 3) * 2);
        #pragma unroll
        for (int nt = 0; nt < 8; nt++) {
            const float jc  = (float)(nt * 8) + jcb;
            const float d00 = i0f - jc, d01 = d00 - 1.0f;
            const float d10 = i1f - jc, d11 = d10 - 1.0f;
            const float p00 = (d00 >= 0.0f) ? ex2(fmaf(S[nt][0], qs, -rl * d00)) : 0.0f;
            const float p01 = (d01 >= 0.0f) ? ex2(fmaf(S[nt][1], qs, -rl * d01)) : 0.0f;
            const float p10 = (d10 >= 0.0f) ? ex2(fmaf(S[nt][2], qs, -rl * d10)) : 0.0f;
            const float p11 = (d11 >= 0.0f) ? ex2(fmaf(S[nt][3], qs, -rl * d11)) : 0.0f;
            lsum0 += p00 + p01;
            lsum1 += p10 + p11;
            const __half h00 = __float2half_rn(p00), h01 = __float2half_rn(p01);
            const __half h10 = __float2half_rn(p10), h11 = __float2half_rn(p11);
            __half2 hh0 = __halves2half2(h00, h01);
            __half2 hh1 = __halves2half2(h10, h11);
            PH0[nt] = *reinterpret_cast<uint32_t*>(&hh0);
            PH1[nt] = *reinterpret_cast<uint32_t*>(&hh1);
            PL0[nt] = pack2(p00 - __half2float(h00), p01 - __half2float(h01));
            PL1[nt] = pack2(p10 - __half2float(h10), p11 - __half2float(h11));
        }

        #pragma unroll
        for (int ks = 0; ks < 4; ks++) {
            const uint32_t a0 = PH0[2*ks], a1 = PH1[2*ks], a2 = PH0[2*ks+1], a3 = PH1[2*ks+1];
            const uint32_t e0 = PL0[2*ks], e1 = PL1[2*ks], e2 = PL0[2*ks+1], e3 = PL1[2*ks+1];
            #pragma unroll
            for (int np = 0; np < 4; np++) {
                uint32_t v0, v1, v2, v3;
                ldsm_x4t(v0, v1, v2, v3,
                         smem_u32(VsH + (ks * 16 + vRow) * KV_STR + np * 16 + vN));
                mma16816(O[2*np],   a0, a1, a2, a3, v0, v1);
                mma16816(O[2*np+1], a0, a1, a2, a3, v2, v3);
                mma16816(O[2*np],   e0, e1, e2, e3, v0, v1);
                mma16816(O[2*np+1], e0, e1, e2, e3, v2, v3);
            }
        }
        buf ^= 1;
    }

    lsum0 += __shfl_xor_sync(0xffffffffu, lsum0, 1);
    lsum0 += __shfl_xor_sync(0xffffffffu, lsum0, 2);
    lsum1 += __shfl_xor_sync(0xffffffffu, lsum1, 1);
    lsum1 += __shfl_xor_sync(0xffffffffu, lsum1, 2);
    const float inv0 = 1.0f / lsum0;
    const float inv1 = 1.0f / lsum1;

    const int irow = q0 + warp * 16 + (lane >> 2);
    const size_t rb0 = (rowBase + irow) * CDIM + h * HD;
    const size_t rb1 = rb0 + (size_t)8 * CDIM;
    #pragma unroll
    for (int nt = 0; nt < 8; nt++) {
        const int col = nt * 8 + (lane & 3) * 2;
        const float y0 = O[nt][0] * inv0, y1 = O[nt][1] * inv0;
        const float y2 = O[nt][2] * inv1, y3 = O[nt][3] * inv1;
        const __half a0 = __float2half_rn(y0), a1 = __float2half_rn(y1);
        const __half a2 = __float2half_rn(y2), a3 = __float2half_rn(y3);
        *(__half2*)(yhi + rb0 + col) = __halves2half2(a0, a1);
        *(__half2*)(yhi + rb1 + col) = __halves2half2(a2, a3);
        *(__half2*)(ylo + rb0 + col) = __halves2half2(
            __float2half_rn(y0 - __half2float(a0)), __float2half_rn(y1 - __half2float(a1)));
        *(__half2*)(ylo + rb1 + col) = __halves2half2(
            __float2half_rn(y2 - __half2float(a2)), __float2half_rn(y3 - __half2float(a3)));
    }
}

// ---------------------------------------------------------------------------
extern "C" void kernel_launch(void* const* d_in, const int* in_sizes, int n_in,
                              void* d_out, int out_size)
{
    const float* x      = (const float*)d_in[0];
    const float* W_attn = (const float*)d_in[1];
    const float* b_attn = (const float*)d_in[2];
    const float* W_proj = (const float*)d_in[3];
    const float* b_proj = (const float*)d_in[4];
    const float* decay  = (const float*)d_in[5];
    float* out = (float*)d_out;

    __half *qkhi, *qklo, *xhi, *xlo, *wahi, *wphi, *yhi, *ylo;
    cudaGetSymbolAddress((void**)&qkhi, g_qkhi);
    cudaGetSymbolAddress((void**)&qklo, g_qklo);
    cudaGetSymbolAddress((void**)&xhi,  g_xhi);
    cudaGetSymbolAddress((void**)&xlo,  g_xlo);
    cudaGetSymbolAddress((void**)&wahi, g_wahi);
    cudaGetSymbolAddress((void**)&wphi, g_wphi);
    cudaGetSymbolAddress((void**)&yhi,  g_yhi);
    cudaGetSymbolAddress((void**)&ylo,  g_ylo);

    static bool attr_set = false;
    if (!attr_set) {
        cudaFuncSetAttribute((const void*)hgemm_split<true>,
                             cudaFuncAttributeMaxDynamicSharedMemorySize, HG_SMEM);
        cudaFuncSetAttribute((const void*)hgemm_split<false>,
                             cudaFuncAttributeMaxDynamicSharedMemorySize, HG_SMEM);
        cudaFuncSetAttribute((const void*)attn_mma,
                             cudaFuncAttributeMaxDynamicSharedMemorySize, AT_SMEM);
        attr_set = true;
    }

    // 0) x: hi/lo split; weights: hi-only convert
    {
        int n4 = MROWS * CDIM / 4;
        split_fp32<<<(n4 + 255) / 256, 256>>>((const float4*)x, (__half2*)xhi, (__half2*)xlo, n4);
        n4 = CDIM * C3 / 4;
        cvt_fp16<<<(n4 + 255) / 256, 256>>>((const float4*)W_attn, (__half2*)wahi, n4);
        n4 = CDIM * CDIM / 4;
        cvt_fp16<<<(n4 + 255) / 256, 256>>>((const float4*)W_proj, (__half2*)wphi, n4);
    }
    // 1) qkv = x @ W_attn + b_attn -> fp16 hi (+lo for Q cols)
    {
        dim3 grid(C3 / 128, MROWS / 128);
        hgemm_split<true><<<grid, 256, HG_SMEM>>>(
            xhi, xlo, wahi, b_attn, nullptr, qkhi, qklo, C3, CDIM);
    }
    // 2) fused decay attention -> yhi/ylo
    {
        dim3 grid(SEQ / 64, NHEAD, BATCH);
        attn_mma<<<grid, 128, AT_SMEM>>>(qkhi, qklo, decay, yhi, ylo);
    }
    // 3) out = y @ W_proj + b_proj -> fp32
    {
        dim3 grid(CDIM / 128, MROWS / 128);
        hgemm_split<false><<<grid, 256, HG_SMEM>>>(
            yhi, ylo, wphi, b_proj, out, nullptr, nullptr, CDIM, CDIM);
    }
}

// round 12
// speedup vs baseline: 1.0120x; 1.0120x over previous
#include <cuda_runtime.h>
#include <cuda_fp16.h>
#include <cstdint>

// Problem constants (fixed by setup_inputs)
#define BATCH 4
#define SEQ   2048
#define CDIM  768
#define NHEAD 12
#define HD    64
#define MROWS (BATCH*SEQ)      // 8192
#define C3    (3*CDIM)         // 2304
#define LOG2E 1.4426950408889634f

// Scratch (device globals; no runtime allocation)
__device__ __half g_qkhi[(size_t)MROWS * C3];
__device__ __half g_qklo[(size_t)MROWS * C3];    // only Q section written/read
__device__ __half g_xhi[(size_t)MROWS * CDIM];
__device__ __half g_xlo[(size_t)MROWS * CDIM];
__device__ __half g_wahi[(size_t)CDIM * C3];     // weights: hi only (split-2)
__device__ __half g_wphi[(size_t)CDIM * CDIM];
__device__ __half g_yhi[(size_t)MROWS * CDIM];
__device__ __half g_ylo[(size_t)MROWS * CDIM];

__device__ __forceinline__ float ex2(float x) {
    float y;
    asm("ex2.approx.f32 %0, %1;" : "=f"(y) : "f"(x));
    return y;
}
__device__ __forceinline__ uint32_t smem_u32(const void* p) {
    return (uint32_t)__cvta_generic_to_shared(p);
}
__device__ __forceinline__ void cp16(uint32_t dst, const void* src) {
    asm volatile("cp.async.ca.shared.global [%0], [%1], 16;\n" :: "r"(dst), "l"(src));
}
__device__ __forceinline__ void cp_commit() {
    asm volatile("cp.async.commit_group;\n" ::: "memory");
}
__device__ __forceinline__ void cp_wait0() {
    asm volatile("cp.async.wait_group 0;\n" ::: "memory");
}
__device__ __forceinline__ void ldsm_x4(uint32_t& r0, uint32_t& r1, uint32_t& r2, uint32_t& r3,
                                        uint32_t addr) {
    asm volatile("ldmatrix.sync.aligned.m8n8.x4.shared.b16 {%0,%1,%2,%3}, [%4];"
                 : "=r"(r0), "=r"(r1), "=r"(r2), "=r"(r3) : "r"(addr));
}
__device__ __forceinline__ void ldsm_x4t(uint32_t& r0, uint32_t& r1, uint32_t& r2, uint32_t& r3,
                                         uint32_t addr) {
    asm volatile("ldmatrix.sync.aligned.m8n8.x4.trans.shared.b16 {%0,%1,%2,%3}, [%4];"
                 : "=r"(r0), "=r"(r1), "=r"(r2), "=r"(r3) : "r"(addr));
}
__device__ __forceinline__ void ldsm_x2t(uint32_t& r0, uint32_t& r1, uint32_t addr) {
    asm volatile("ldmatrix.sync.aligned.m8n8.x2.trans.shared.b16 {%0,%1}, [%2];"
                 : "=r"(r0), "=r"(r1) : "r"(addr));
}
__device__ __forceinline__ void mma16816(float* c,
                                         uint32_t a0, uint32_t a1, uint32_t a2, uint32_t a3,
                                         uint32_t b0, uint32_t b1) {
    asm volatile("mma.sync.aligned.m16n8k16.row.col.f32.f16.f16.f32 "
                 "{%0,%1,%2,%3}, {%4,%5,%6,%7}, {%8,%9}, {%0,%1,%2,%3};"
                 : "+f"(c[0]), "+f"(c[1]), "+f"(c[2]), "+f"(c[3])
                 : "r"(a0), "r"(a1), "r"(a2), "r"(a3), "r"(b0), "r"(b1));
}
__device__ __forceinline__ uint32_t pack2(float a, float b) {
    __half2 h = __halves2half2(__float2half_rn(a), __float2half_rn(b));
    return *reinterpret_cast<uint32_t*>(&h);
}

// ---------------------------------------------------------------------------
// fp32 -> (fp16 hi, fp16 lo) split, vectorized by 4. (A operands)
// ---------------------------------------------------------------------------
__global__ void __launch_bounds__(256) split_fp32(
    const float4* __restrict__ src, __half2* __restrict__ hi,
    __half2* __restrict__ lo, int n4)
{
    const int i = blockIdx.x * blockDim.x + threadIdx.x;
    if (i >= n4) return;
    float4 v = src[i];
    __half h0 = __float2half_rn(v.x), h1 = __float2half_rn(v.y);
    __half h2 = __float2half_rn(v.z), h3 = __float2half_rn(v.w);
    hi[2*i]   = __halves2half2(h0, h1);
    hi[2*i+1] = __halves2half2(h2, h3);
    lo[2*i]   = __halves2half2(__float2half_rn(v.x - __half2float(h0)),
                               __float2half_rn(v.y - __half2float(h1)));
    lo[2*i+1] = __halves2half2(__float2half_rn(v.z - __half2float(h2)),
                               __float2half_rn(v.w - __half2float(h3)));
}

// fp32 -> fp16 convert only (B operands: hi part only)
__global__ void __launch_bounds__(256) cvt_fp16(
    const float4* __restrict__ src, __half2* __restrict__ hi, int n4)
{
    const int i = blockIdx.x * blockDim.x + threadIdx.x;
    if (i >= n4) return;
    float4 v = src[i];
    hi[2*i]   = __halves2half2(__float2half_rn(v.x), __float2half_rn(v.y));
    hi[2*i+1] = __halves2half2(__float2half_rn(v.z), __float2half_rn(v.w));
}

// ---------------------------------------------------------------------------
// Split-2 fp16 tensor-core GEMM + bias, cp.async double-buffered, BK=64.
//   C = (Ahi+Alo) @ Bhi + bias
// R10-proven 2-stage mainloop (prefetch at top, wait0+sync at bottom),
// BK doubled 32->64: 4 k16 sub-steps per sync window (half the barriers).
// OUT_HALF: write hi/lo fp16 (lo only for Q columns c<CDIM). Else fp32.
// BM=128, 256 threads = 8 warps (2x4 grid, 64x32 per warp).
// ---------------------------------------------------------------------------
#define BK    64
#define A_STR 72    // halves per A smem row (64 + 8 pad)
#define B_STR 136
#define HG_ABUF (128 * A_STR)                    // 9216 halves
#define HG_BBUF (BK * B_STR)                     // 8704 halves
#define HG_STAGE (2 * HG_ABUF + HG_BBUF)         // 27136 halves
#define HG_SMEM  (2 * HG_STAGE * 2)              // ~106 KB

template<bool OUT_HALF>
__global__ void __launch_bounds__(256, 2) hgemm_split(
    const __half* __restrict__ Ahi, const __half* __restrict__ Alo,
    const __half* __restrict__ Bhi,
    const float* __restrict__ bias, float* __restrict__ C,
    __half* __restrict__ Chi, __half* __restrict__ Clo,
    int N, int K)
{
    extern __shared__ __align__(16) __half hsm[];

    const int t    = threadIdx.x;
    const int warp = t >> 5;
    const int lane = t & 31;
    const int wm   = (warp & 1) * 64;
    const int wn   = (warp >> 1) * 32;

    const size_t aG   = (size_t)blockIdx.y * 128 * K;
    const int    bCol = blockIdx.x * 128;

    const int g     = lane >> 3;
    const int lr    = lane & 7;
    const int aRowF = (g & 1) * 8 + lr;
    const int aColF = (g >> 1) * 8;
    const int bRowF = ((lane >> 3) & 1) * 8 + lr;

    float acc[4][4][4];
    #pragma unroll
    for (int mt = 0; mt < 4; mt++)
        #pragma unroll
        for (int nt = 0; nt < 4; nt++)
            #pragma unroll
            for (int i = 0; i < 4; i++) acc[mt][nt][i] = 0.0f;

    auto load_tile = [&](int s, int ko) {
        __half* base = hsm + s * HG_STAGE;
        __half* aH = base;
        __half* aL = base + HG_ABUF;
        __half* bH = base + 2 * HG_ABUF;
        // A: 128 rows x 64 halves = 1024 16B-chunks -> 4 iters x 256 thr
        #pragma unroll
        for (int it = 0; it < 4; it++) {
            const int u   = it * 256 + t;
            const int row = u >> 3;
            const int c   = (u & 7) * 8;
            const size_t gsrc = aG + (size_t)row * K + ko + c;
            cp16(smem_u32(aH + row * A_STR + c), Ahi + gsrc);
            cp16(smem_u32(aL + row * A_STR + c), Alo + gsrc);
        }
        // B: 64 rows x 128 halves = 1024 16B-chunks -> 4 iters x 256 thr
        #pragma unroll
        for (int it = 0; it < 4; it++) {
            const int u   = it * 256 + t;
            const int row = u >> 4;
            const int c   = (u & 15) * 8;
            cp16(smem_u32(bH + row * B_STR + c), Bhi + (size_t)(ko + row) * N + bCol + c);
        }
        cp_commit();
    };

    load_tile(0, 0);
    cp_wait0();
    __syncthreads();

    const int nk = K / BK;   // 12
    int buf = 0;
    for (int kt = 0; kt < nk; kt++) {
        if (kt + 1 < nk) load_tile(buf ^ 1, (kt + 1) * BK);

        const __half* base = hsm + buf * HG_STAGE;
        const __half* aH = base;
        const __half* aL = base + HG_ABUF;
        const __half* bH = base + 2 * HG_ABUF;

        #pragma unroll
        for (int ks = 0; ks < 4; ks++) {
            uint32_t afh[4][4], afl[4][4], bfh[4][2];
            #pragma unroll
            for (int mt = 0; mt < 4; mt++) {
                const int row = wm + mt * 16 + aRowF;
                ldsm_x4(afh[mt][0], afh[mt][1], afh[mt][2], afh[mt][3],
                        smem_u32(aH + row * A_STR + ks * 16 + aColF));
                ldsm_x4(afl[mt][0], afl[mt][1], afl[mt][2], afl[mt][3],
                        smem_u32(aL + row * A_STR + ks * 16 + aColF));
            }
            #pragma unroll
            for (int nt = 0; nt < 4; nt++) {
                const int col = wn + nt * 8;
                ldsm_x2t(bfh[nt][0], bfh[nt][1],
                         smem_u32(bH + (ks * 16 + bRowF) * B_STR + col));
            }
            #pragma unroll
            for (int mt = 0; mt < 4; mt++)
                #pragma unroll
                for (int nt = 0; nt < 4; nt++) {
                    mma16816(acc[mt][nt], afh[mt][0], afh[mt][1], afh[mt][2], afh[mt][3],
                             bfh[nt][0], bfh[nt][1]);
                    mma16816(acc[mt][nt], afl[mt][0], afl[mt][1], afl[mt][2], afl[mt][3],
                             bfh[nt][0], bfh[nt][1]);
                }
        }

        if (kt + 1 < nk) {
            cp_wait0();
            __syncthreads();
            buf ^= 1;
        }
    }

    #pragma unroll
    for (int mt = 0; mt < 4; mt++) {
        const int r0 = blockIdx.y * 128 + wm + mt * 16 + (lane >> 2);
        #pragma unroll
        for (int nt = 0; nt < 4; nt++) {
            const int c0 = bCol + wn + nt * 8 + (lane & 3) * 2;
            const float b0 = bias[c0], b1 = bias[c0 + 1];
            const float v00 = acc[mt][nt][0] + b0, v01 = acc[mt][nt][1] + b1;
            const float v10 = acc[mt][nt][2] + b0, v11 = acc[mt][nt][3] + b1;
            if (OUT_HALF) {
                const __half h00 = __float2half_rn(v00), h01 = __float2half_rn(v01);
                const __half h10 = __float2half_rn(v10), h11 = __float2half_rn(v11);
                *(__half2*)(Chi + (size_t)r0 * N + c0)       = __halves2half2(h00, h01);
                *(__half2*)(Chi + (size_t)(r0 + 8) * N + c0) = __halves2half2(h10, h11);
                if (c0 < CDIM) {   // lo only consumed for Q columns
                    *(__half2*)(Clo + (size_t)r0 * N + c0)       = __halves2half2(
                        __float2half_rn(v00 - __half2float(h00)),
                        __float2half_rn(v01 - __half2float(h01)));
                    *(__half2*)(Clo + (size_t)(r0 + 8) * N + c0) = __halves2half2(
                        __float2half_rn(v10 - __half2float(h10)),
                        __float2half_rn(v11 - __half2float(h11)));
                }
            } else {
                *(float2*)(C + (size_t)r0 * N + c0)       = make_float2(v00, v01);
                *(float2*)(C + (size_t)(r0 + 8) * N + c0) = make_float2(v10, v11);
            }
        }
    }
}

// ---------------------------------------------------------------------------
// Tensor-core flash attention, split-2 (unchanged from R11):
//   S = (Qhi+Qlo)@Khi^T, P = exp2(S*qs - rl*dist), O = (Phi+Plo)@Vhi.
// 3 CTAs/SM. Window: r*dist > 16 -> tile-skipped.
// ---------------------------------------------------------------------------
#define KV_STR 72
#define AT_BUF (64 * KV_STR)
#define AT_STAGE (2 * AT_BUF)                 // K hi, V hi
#define AT_SMEM ((2 * AT_BUF + 2 * AT_STAGE) * 2)   // bytes (~55 KB)

__global__ void __launch_bounds__(128, 3) attn_mma(
    const __half* __restrict__ qkhi, const __half* __restrict__ qklo,
    const float* __restrict__ decay,
    __half* __restrict__ yhi, __half* __restrict__ ylo)
{
    extern __shared__ __align__(16) __half asm_[];
    __half* QsH = asm_;
    __half* QsL = asm_ + AT_BUF;

    const int q0   = blockIdx.x * 64;
    const int h    = blockIdx.y;
    const int bb   = blockIdx.z;
    const int t    = threadIdx.x;
    const int warp = t >> 5;
    const int lane = t & 31;

    const size_t rowBase = (size_t)bb * SEQ;
    const float r  = decay[h];
    const float rl = r * LOG2E;
    const float qs = 0.125f * LOG2E;

    {
        #pragma unroll
        for (int it = 0; it < 4; it++) {
            const int u = it * 128 + t;
            const int row = u >> 3;
            const int c = (u & 7) * 8;
            const size_t gsrc = (rowBase + q0 + row) * C3 + h * HD + c;
            cp16(smem_u32(QsH + row * KV_STR + c), qkhi + gsrc);
            cp16(smem_u32(QsL + row * KV_STR + c), qklo + gsrc);
        }
        cp_commit();
    }

    auto load_kv = [&](int s, int k0) {
        __half* st = asm_ + 2 * AT_BUF + s * AT_STAGE;
        __half* kH = st;
        __half* vH = st + AT_BUF;
        #pragma unroll
        for (int it = 0; it < 4; it++) {
            const int u = it * 128 + t;
            const int row = u >> 3;
            const int c = (u & 7) * 8;
            const size_t gk = (rowBase + k0 + row) * C3 + CDIM + h * HD + c;
            cp16(smem_u32(kH + row * KV_STR + c), qkhi + gk);
            cp16(smem_u32(vH + row * KV_STR + c), qkhi + gk + CDIM);
        }
        cp_commit();
    };

    const int W = (r > 1e-6f) ? (int)(16.0f / r) : (1 << 30);
    int km = q0 - W;
    if (km < 0) km = 0;
    const int kstart = (km / 64) * 64;

    load_kv(0, kstart);
    cp_wait0();
    __syncthreads();

    const int lr   = lane & 7;
    const int aRow = lr + ((lane >> 3) & 1) * 8;
    const int aCol = (lane >> 4) * 8;
    const int kN   = ((lane >> 4) & 1) * 8;
    const int kK   = ((lane >> 3) & 1) * 8;
    const int vRow = lane & 15;
    const int vN   = (lane >> 4) * 8;

    uint32_t qh[4][4], ql[4][4];
    #pragma unroll
    for (int ks = 0; ks < 4; ks++) {
        ldsm_x4(qh[ks][0], qh[ks][1], qh[ks][2], qh[ks][3],
                smem_u32(QsH + (warp * 16 + aRow) * KV_STR + ks * 16 + aCol));
        ldsm_x4(ql[ks][0], ql[ks][1], ql[ks][2], ql[ks][3],
                smem_u32(QsL + (warp * 16 + aRow) * KV_STR + ks * 16 + aCol));
    }

    float O[8][4];
    #pragma unroll
    for (int nt = 0; nt < 8; nt++)
        #pragma unroll
        for (int i = 0; i < 4; i++) O[nt][i] = 0.0f;
    float lsum0 = 0.0f, lsum1 = 0.0f;

    int buf = 0;
    for (int k0 = kstart; k0 <= q0; k0 += 64) {
        if (k0 != kstart) {
            cp_wait0();
            __syncthreads();
        }
        if (k0 + 64 <= q0) load_kv(buf ^ 1, k0 + 64);

        __half* st = asm_ + 2 * AT_BUF + buf * AT_STAGE;
        const __half* KsH = st;
        const __half* VsH = st + AT_BUF;

        float S[8][4];
        #pragma unroll
        for (int nt = 0; nt < 8; nt++)
            #pragma unroll
            for (int i = 0; i < 4; i++) S[nt][i] = 0.0f;

        #pragma unroll
        for (int ks = 0; ks < 4; ks++) {
            #pragma unroll
            for (int np = 0; np < 4; np++) {
                uint32_t b0, b1, b2, b3;
                ldsm_x4(b0, b1, b2, b3,
                        smem_u32(KsH + (np * 16 + kN + lr) * KV_STR + ks * 16 + kK));
                mma16816(S[2*np],   qh[ks][0], qh[ks][1], qh[ks][2], qh[ks][3], b0, b1);
                mma16816(S[2*np+1], qh[ks][0], qh[ks][1], qh[ks][2], qh[ks][3], b2, b3);
                mma16816(S[2*np],   ql[ks][0], ql[ks][1], ql[ks][2], ql[ks][3], b0, b1);
                mma16816(S[2*np+1], ql[ks][0], ql[ks][1], ql[ks][2], ql[ks][3], b2, b3);
            }
        }

        uint32_t PH0[8], PH1[8], PL0[8], PL1[8];
        const float i0f = (float)(q0 + warp * 16 + (lane >> 2) - k0);
        const float i1f = i0f + 8.0f;
        const float jcb = (float)((lane & 3) * 2);
        #pragma unroll
        for (int nt = 0; nt < 8; nt++) {
            const float jc  = (float)(nt * 8) + jcb;
            const float d00 = i0f - jc, d01 = d00 - 1.0f;
            const float d10 = i1f - jc, d11 = d10 - 1.0f;
            const float p00 = (d00 >= 0.0f) ? ex2(fmaf(S[nt][0], qs, -rl * d00)) : 0.0f;
            const float p01 = (d01 >= 0.0f) ? ex2(fmaf(S[nt][1], qs, -rl * d01)) : 0.0f;
            const float p10 = (d10 >= 0.0f) ? ex2(fmaf(S[nt][2], qs, -rl * d10)) : 0.0f;
            const float p11 = (d11 >= 0.0f) ? ex2(fmaf(S[nt][3], qs, -rl * d11)) : 0.0f;
            lsum0 += p00 + p01;
            lsum1 += p10 + p11;
            const __half h00 = __float2half_rn(p00), h01 = __float2half_rn(p01);
            const __half h10 = __float2half_rn(p10), h11 = __float2half_rn(p11);
            __half2 hh0 = __halves2half2(h00, h01);
            __half2 hh1 = __halves2half2(h10, h11);
            PH0[nt] = *reinterpret_cast<uint32_t*>(&hh0);
            PH1[nt] = *reinterpret_cast<uint32_t*>(&hh1);
            PL0[nt] = pack2(p00 - __half2float(h00), p01 - __half2float(h01));
            PL1[nt] = pack2(p10 - __half2float(h10), p11 - __half2float(h11));
        }

        #pragma unroll
        for (int ks = 0; ks < 4; ks++) {
            const uint32_t a0 = PH0[2*ks], a1 = PH1[2*ks], a2 = PH0[2*ks+1], a3 = PH1[2*ks+1];
            const uint32_t e0 = PL0[2*ks], e1 = PL1[2*ks], e2 = PL0[2*ks+1], e3 = PL1[2*ks+1];
            #pragma unroll
            for (int np = 0; np < 4; np++) {
                uint32_t v0, v1, v2, v3;
                ldsm_x4t(v0, v1, v2, v3,
                         smem_u32(VsH + (ks * 16 + vRow) * KV_STR + np * 16 + vN));
                mma16816(O[2*np],   a0, a1, a2, a3, v0, v1);
                mma16816(O[2*np+1], a0, a1, a2, a3, v2, v3);
                mma16816(O[2*np],   e0, e1, e2, e3, v0, v1);
                mma16816(O[2*np+1], e0, e1, e2, e3, v2, v3);
            }
        }
        buf ^= 1;
    }

    lsum0 += __shfl_xor_sync(0xffffffffu, lsum0, 1);
    lsum0 += __shfl_xor_sync(0xffffffffu, lsum0, 2);
    lsum1 += __shfl_xor_sync(0xffffffffu, lsum1, 1);
    lsum1 += __shfl_xor_sync(0xffffffffu, lsum1, 2);
    const float inv0 = 1.0f / lsum0;
    const float inv1 = 1.0f / lsum1;

    const int irow = q0 + warp * 16 + (lane >> 2);
    const size_t rb0 = (rowBase + irow) * CDIM + h * HD;
    const size_t rb1 = rb0 + (size_t)8 * CDIM;
    #pragma unroll
    for (int nt = 0; nt < 8; nt++) {
        const int col = nt * 8 + (lane & 3) * 2;
        const float y0 = O[nt][0] * inv0, y1 = O[nt][1] * inv0;
        const float y2 = O[nt][2] * inv1, y3 = O[nt][3] * inv1;
        const __half a0 = __float2half_rn(y0), a1 = __float2half_rn(y1);
        const __half a2 = __float2half_rn(y2), a3 = __float2half_rn(y3);
        *(__half2*)(yhi + rb0 + col) = __halves2half2(a0, a1);
        *(__half2*)(yhi + rb1 + col) = __halves2half2(a2, a3);
        *(__half2*)(ylo + rb0 + col) = __halves2half2(
            __float2half_rn(y0 - __half2float(a0)), __float2half_rn(y1 - __half2float(a1)));
        *(__half2*)(ylo + rb1 + col) = __halves2half2(
            __float2half_rn(y2 - __half2float(a2)), __float2half_rn(y3 - __half2float(a3)));
    }
}

// ---------------------------------------------------------------------------
extern "C" void kernel_launch(void* const* d_in, const int* in_sizes, int n_in,
                              void* d_out, int out_size)
{
    const float* x      = (const float*)d_in[0];
    const float* W_attn = (const float*)d_in[1];
    const float* b_attn = (const float*)d_in[2];
    const float* W_proj = (const float*)d_in[3];
    const float* b_proj = (const float*)d_in[4];
    const float* decay  = (const float*)d_in[5];
    float* out = (float*)d_out;

    __half *qkhi, *qklo, *xhi, *xlo, *wahi, *wphi, *yhi, *ylo;
    cudaGetSymbolAddress((void**)&qkhi, g_qkhi);
    cudaGetSymbolAddress((void**)&qklo, g_qklo);
    cudaGetSymbolAddress((void**)&xhi,  g_xhi);
    cudaGetSymbolAddress((void**)&xlo,  g_xlo);
    cudaGetSymbolAddress((void**)&wahi, g_wahi);
    cudaGetSymbolAddress((void**)&wphi, g_wphi);
    cudaGetSymbolAddress((void**)&yhi,  g_yhi);
    cudaGetSymbolAddress((void**)&ylo,  g_ylo);

    static bool attr_set = false;
    if (!attr_set) {
        cudaFuncSetAttribute((const void*)hgemm_split<true>,
                             cudaFuncAttributeMaxDynamicSharedMemorySize, HG_SMEM);
        cudaFuncSetAttribute((const void*)hgemm_split<false>,
                             cudaFuncAttributeMaxDynamicSharedMemorySize, HG_SMEM);
        cudaFuncSetAttribute((const void*)attn_mma,
                             cudaFuncAttributeMaxDynamicSharedMemorySize, AT_SMEM);
        attr_set = true;
    }

    // 0) x: hi/lo split; weights: hi-only convert
    {
        int n4 = MROWS * CDIM / 4;
        split_fp32<<<(n4 + 255) / 256, 256>>>((const float4*)x, (__half2*)xhi, (__half2*)xlo, n4);
        n4 = CDIM * C3 / 4;
        cvt_fp16<<<(n4 + 255) / 256, 256>>>((const float4*)W_attn, (__half2*)wahi, n4);
        n4 = CDIM * CDIM / 4;
        cvt_fp16<<<(n4 + 255) / 256, 256>>>((const float4*)W_proj, (__half2*)wphi, n4);
    }
    // 1) qkv = x @ W_attn + b_attn -> fp16 hi (+lo for Q cols)
    {
        dim3 grid(C3 / 128, MROWS / 128);
        hgemm_split<true><<<grid, 256, HG_SMEM>>>(
            xhi, xlo, wahi, b_attn, nullptr, qkhi, qklo, C3, CDIM);
    }
    // 2) fused decay attention -> yhi/ylo
    {
        dim3 grid(SEQ / 64, NHEAD, BATCH);
        attn_mma<<<grid, 128, AT_SMEM>>>(qkhi, qklo, decay, yhi, ylo);
    }
    // 3) out = y @ W_proj + b_proj -> fp32
    {
        dim3 grid(CDIM / 128, MROWS / 128);
        hgemm_split<false><<<grid, 256, HG_SMEM>>>(
            yhi, ylo, wphi, b_proj, out, nullptr, nullptr, CDIM, CDIM);
    }
}

// round 13
// speedup vs baseline: 1.0356x; 1.0233x over previous
#include <cuda_runtime.h>
#include <cuda_fp16.h>
#include <cstdint>

// Problem constants (fixed by setup_inputs)
#define BATCH 4
#define SEQ   2048
#define CDIM  768
#define NHEAD 12
#define HD    64
#define MROWS (BATCH*SEQ)      // 8192
#define C3    (3*CDIM)         // 2304
#define LOG2E 1.4426950408889634f

// Scratch (device globals; no runtime allocation)
__device__ __half g_qkhi[(size_t)MROWS * C3];
__device__ __half g_qklo[(size_t)MROWS * C3];    // only Q section written/read
__device__ __half g_xhi[(size_t)MROWS * CDIM];
__device__ __half g_xlo[(size_t)MROWS * CDIM];
__device__ __half g_wahi[(size_t)CDIM * C3];     // weights: hi only (split-2)
__device__ __half g_wphi[(size_t)CDIM * CDIM];
__device__ __half g_yhi[(size_t)MROWS * CDIM];
__device__ __half g_ylo[(size_t)MROWS * CDIM];

__device__ __forceinline__ float ex2(float x) {
    float y;
    asm("ex2.approx.f32 %0, %1;" : "=f"(y) : "f"(x));
    return y;
}
__device__ __forceinline__ uint32_t smem_u32(const void* p) {
    return (uint32_t)__cvta_generic_to_shared(p);
}
__device__ __forceinline__ void cp16(uint32_t dst, const void* src) {
    asm volatile("cp.async.ca.shared.global [%0], [%1], 16;\n" :: "r"(dst), "l"(src));
}
__device__ __forceinline__ void cp_commit() {
    asm volatile("cp.async.commit_group;\n" ::: "memory");
}
__device__ __forceinline__ void cp_wait0() {
    asm volatile("cp.async.wait_group 0;\n" ::: "memory");
}
__device__ __forceinline__ void ldsm_x4(uint32_t& r0, uint32_t& r1, uint32_t& r2, uint32_t& r3,
                                        uint32_t addr) {
    asm volatile("ldmatrix.sync.aligned.m8n8.x4.shared.b16 {%0,%1,%2,%3}, [%4];"
                 : "=r"(r0), "=r"(r1), "=r"(r2), "=r"(r3) : "r"(addr));
}
__device__ __forceinline__ void ldsm_x4t(uint32_t& r0, uint32_t& r1, uint32_t& r2, uint32_t& r3,
                                         uint32_t addr) {
    asm volatile("ldmatrix.sync.aligned.m8n8.x4.trans.shared.b16 {%0,%1,%2,%3}, [%4];"
                 : "=r"(r0), "=r"(r1), "=r"(r2), "=r"(r3) : "r"(addr));
}
__device__ __forceinline__ void ldsm_x2t(uint32_t& r0, uint32_t& r1, uint32_t addr) {
    asm volatile("ldmatrix.sync.aligned.m8n8.x2.trans.shared.b16 {%0,%1}, [%2];"
                 : "=r"(r0), "=r"(r1) : "r"(addr));
}
__device__ __forceinline__ void mma16816(float* c,
                                         uint32_t a0, uint32_t a1, uint32_t a2, uint32_t a3,
                                         uint32_t b0, uint32_t b1) {
    asm volatile("mma.sync.aligned.m16n8k16.row.col.f32.f16.f16.f32 "
                 "{%0,%1,%2,%3}, {%4,%5,%6,%7}, {%8,%9}, {%0,%1,%2,%3};"
                 : "+f"(c[0]), "+f"(c[1]), "+f"(c[2]), "+f"(c[3])
                 : "r"(a0), "r"(a1), "r"(a2), "r"(a3), "r"(b0), "r"(b1));
}
__device__ __forceinline__ uint32_t pack2(float a, float b) {
    __half2 h = __halves2half2(__float2half_rn(a), __float2half_rn(b));
    return *reinterpret_cast<uint32_t*>(&h);
}

// ---------------------------------------------------------------------------
// fp32 -> (fp16 hi, fp16 lo) split, vectorized by 4. (A operands)
// ---------------------------------------------------------------------------
__global__ void __launch_bounds__(256) split_fp32(
    const float4* __restrict__ src, __half2* __restrict__ hi,
    __half2* __restrict__ lo, int n4)
{
    const int i = blockIdx.x * blockDim.x + threadIdx.x;
    if (i >= n4) return;
    float4 v = src[i];
    __half h0 = __float2half_rn(v.x), h1 = __float2half_rn(v.y);
    __half h2 = __float2half_rn(v.z), h3 = __float2half_rn(v.w);
    hi[2*i]   = __halves2half2(h0, h1);
    hi[2*i+1] = __halves2half2(h2, h3);
    lo[2*i]   = __halves2half2(__float2half_rn(v.x - __half2float(h0)),
                               __float2half_rn(v.y - __half2float(h1)));
    lo[2*i+1] = __halves2half2(__float2half_rn(v.z - __half2float(h2)),
                               __float2half_rn(v.w - __half2float(h3)));
}

// fp32 -> fp16 convert only (B operands: hi part only)
__global__ void __launch_bounds__(256) cvt_fp16(
    const float4* __restrict__ src, __half2* __restrict__ hi, int n4)
{
    const int i = blockIdx.x * blockDim.x + threadIdx.x;
    if (i >= n4) return;
    float4 v = src[i];
    hi[2*i]   = __halves2half2(__float2half_rn(v.x), __float2half_rn(v.y));
    hi[2*i+1] = __halves2half2(__float2half_rn(v.z), __float2half_rn(v.w));
}

// ---------------------------------------------------------------------------
// Split-2 fp16 tensor-core GEMM + bias, cp.async double-buffered, BK=32.
//   C = (Ahi+Alo) @ Bhi + bias
// EXACT R10 measured-best mainloop (166us GEMM1, tensor 58.4%).
// OUT_HALF: write hi/lo fp16 (lo only for Q columns c<CDIM). Else fp32.
// BM=128, BK=32, 256 threads = 8 warps (2x4 grid, 64x32 per warp).
// ---------------------------------------------------------------------------
#define BK    32
#define A_STR 40
#define B_STR 136
#define HG_ABUF (128 * A_STR)
#define HG_BBUF (BK * B_STR)
#define HG_STAGE (2 * HG_ABUF + HG_BBUF)         // halves
#define HG_SMEM  (2 * HG_STAGE * 2)              // bytes (~58 KB)

template<bool OUT_HALF>
__global__ void __launch_bounds__(256, 2) hgemm_split(
    const __half* __restrict__ Ahi, const __half* __restrict__ Alo,
    const __half* __restrict__ Bhi,
    const float* __restrict__ bias, float* __restrict__ C,
    __half* __restrict__ Chi, __half* __restrict__ Clo,
    int N, int K)
{
    extern __shared__ __align__(16) __half hsm[];

    const int t    = threadIdx.x;
    const int warp = t >> 5;
    const int lane = t & 31;
    const int wm   = (warp & 1) * 64;
    const int wn   = (warp >> 1) * 32;

    const size_t aG   = (size_t)blockIdx.y * 128 * K;
    const int    bCol = blockIdx.x * 128;

    const int g     = lane >> 3;
    const int lr    = lane & 7;
    const int aRowF = (g & 1) * 8 + lr;
    const int aColF = (g >> 1) * 8;
    const int bRowF = ((lane >> 3) & 1) * 8 + lr;

    float acc[4][4][4];
    #pragma unroll
    for (int mt = 0; mt < 4; mt++)
        #pragma unroll
        for (int nt = 0; nt < 4; nt++)
            #pragma unroll
            for (int i = 0; i < 4; i++) acc[mt][nt][i] = 0.0f;

    auto load_tile = [&](int s, int ko) {
        __half* base = hsm + s * HG_STAGE;
        __half* aH = base;
        __half* aL = base + HG_ABUF;
        __half* bH = base + 2 * HG_ABUF;
        #pragma unroll
        for (int it = 0; it < 2; it++) {
            const int u   = it * 256 + t;
            const int row = u >> 2;
            const int c   = (u & 3) * 8;
            const size_t gsrc = aG + (size_t)row * K + ko + c;
            cp16(smem_u32(aH + row * A_STR + c), Ahi + gsrc);
            cp16(smem_u32(aL + row * A_STR + c), Alo + gsrc);
        }
        #pragma unroll
        for (int it = 0; it < 2; it++) {
            const int u   = it * 256 + t;
            const int row = u >> 4;
            const int c   = (u & 15) * 8;
            cp16(smem_u32(bH + row * B_STR + c), Bhi + (size_t)(ko + row) * N + bCol + c);
        }
        cp_commit();
    };

    load_tile(0, 0);
    cp_wait0();
    __syncthreads();

    const int nk = K / BK;
    int buf = 0;
    for (int kt = 0; kt < nk; kt++) {
        if (kt + 1 < nk) load_tile(buf ^ 1, (kt + 1) * BK);

        const __half* base = hsm + buf * HG_STAGE;
        const __half* aH = base;
        const __half* aL = base + HG_ABUF;
        const __half* bH = base + 2 * HG_ABUF;

        #pragma unroll
        for (int ks = 0; ks < 2; ks++) {
            uint32_t afh[4][4], afl[4][4], bfh[4][2];
            #pragma unroll
            for (int mt = 0; mt < 4; mt++) {
                const int row = wm + mt * 16 + aRowF;
                ldsm_x4(afh[mt][0], afh[mt][1], afh[mt][2], afh[mt][3],
                        smem_u32(aH + row * A_STR + ks * 16 + aColF));
                ldsm_x4(afl[mt][0], afl[mt][1], afl[mt][2], afl[mt][3],
                        smem_u32(aL + row * A_STR + ks * 16 + aColF));
            }
            #pragma unroll
            for (int nt = 0; nt < 4; nt++) {
                const int col = wn + nt * 8;
                ldsm_x2t(bfh[nt][0], bfh[nt][1],
                         smem_u32(bH + (ks * 16 + bRowF) * B_STR + col));
            }
            #pragma unroll
            for (int mt = 0; mt < 4; mt++)
                #pragma unroll
                for (int nt = 0; nt < 4; nt++) {
                    mma16816(acc[mt][nt], afh[mt][0], afh[mt][1], afh[mt][2], afh[mt][3],
                             bfh[nt][0], bfh[nt][1]);
                    mma16816(acc[mt][nt], afl[mt][0], afl[mt][1], afl[mt][2], afl[mt][3],
                             bfh[nt][0], bfh[nt][1]);
                }
        }

        if (kt + 1 < nk) {
            cp_wait0();
            __syncthreads();
            buf ^= 1;
        }
    }

    #pragma unroll
    for (int mt = 0; mt < 4; mt++) {
        const int r0 = blockIdx.y * 128 + wm + mt * 16 + (lane >> 2);
        #pragma unroll
        for (int nt = 0; nt < 4; nt++) {
            const int c0 = bCol + wn + nt * 8 + (lane & 3) * 2;
            const float b0 = bias[c0], b1 = bias[c0 + 1];
            const float v00 = acc[mt][nt][0] + b0, v01 = acc[mt][nt][1] + b1;
            const float v10 = acc[mt][nt][2] + b0, v11 = acc[mt][nt][3] + b1;
            if (OUT_HALF) {
                const __half h00 = __float2half_rn(v00), h01 = __float2half_rn(v01);
                const __half h10 = __float2half_rn(v10), h11 = __float2half_rn(v11);
                *(__half2*)(Chi + (size_t)r0 * N + c0)       = __halves2half2(h00, h01);
                *(__half2*)(Chi + (size_t)(r0 + 8) * N + c0) = __halves2half2(h10, h11);
                if (c0 < CDIM) {   // lo only consumed for Q columns
                    *(__half2*)(Clo + (size_t)r0 * N + c0)       = __halves2half2(
                        __float2half_rn(v00 - __half2float(h00)),
                        __float2half_rn(v01 - __half2float(h01)));
                    *(__half2*)(Clo + (size_t)(r0 + 8) * N + c0) = __halves2half2(
                        __float2half_rn(v10 - __half2float(h10)),
                        __float2half_rn(v11 - __half2float(h11)));
                }
            } else {
                *(float2*)(C + (size_t)r0 * N + c0)       = make_float2(v00, v01);
                *(float2*)(C + (size_t)(r0 + 8) * N + c0) = make_float2(v10, v11);
            }
        }
    }
}

// ---------------------------------------------------------------------------
// Tensor-core flash attention, split-2:
//   S = (Qhi+Qlo)@Khi^T, P = exp2(S*qs - rl*dist), O = (Phi+Plo)@Vhi.
// 3 CTAs/SM. Window 14/r: dropped tail weight <= ~2e-5 relative.
// ---------------------------------------------------------------------------
#define KV_STR 72
#define AT_BUF (64 * KV_STR)
#define AT_STAGE (2 * AT_BUF)                 // K hi, V hi
#define AT_SMEM ((2 * AT_BUF + 2 * AT_STAGE) * 2)   // bytes (~55 KB)

__global__ void __launch_bounds__(128, 3) attn_mma(
    const __half* __restrict__ qkhi, const __half* __restrict__ qklo,
    const float* __restrict__ decay,
    __half* __restrict__ yhi, __half* __restrict__ ylo)
{
    extern __shared__ __align__(16) __half asm_[];
    __half* QsH = asm_;
    __half* QsL = asm_ + AT_BUF;

    const int q0   = blockIdx.x * 64;
    const int h    = blockIdx.y;
    const int bb   = blockIdx.z;
    const int t    = threadIdx.x;
    const int warp = t >> 5;
    const int lane = t & 31;

    const size_t rowBase = (size_t)bb * SEQ;
    const float r  = decay[h];
    const float rl = r * LOG2E;
    const float qs = 0.125f * LOG2E;

    {
        #pragma unroll
        for (int it = 0; it < 4; it++) {
            const int u = it * 128 + t;
            const int row = u >> 3;
            const int c = (u & 7) * 8;
            const size_t gsrc = (rowBase + q0 + row) * C3 + h * HD + c;
            cp16(smem_u32(QsH + row * KV_STR + c), qkhi + gsrc);
            cp16(smem_u32(QsL + row * KV_STR + c), qklo + gsrc);
        }
        cp_commit();
    }

    auto load_kv = [&](int s, int k0) {
        __half* st = asm_ + 2 * AT_BUF + s * AT_STAGE;
        __half* kH = st;
        __half* vH = st + AT_BUF;
        #pragma unroll
        for (int it = 0; it < 4; it++) {
            const int u = it * 128 + t;
            const int row = u >> 3;
            const int c = (u & 7) * 8;
            const size_t gk = (rowBase + k0 + row) * C3 + CDIM + h * HD + c;
            cp16(smem_u32(kH + row * KV_STR + c), qkhi + gk);
            cp16(smem_u32(vH + row * KV_STR + c), qkhi + gk + CDIM);
        }
        cp_commit();
    };

    const int W = (r > 1e-6f) ? (int)(14.0f / r) : (1 << 30);
    int km = q0 - W;
    if (km < 0) km = 0;
    const int kstart = (km / 64) * 64;

    load_kv(0, kstart);
    cp_wait0();
    __syncthreads();

    const int lr   = lane & 7;
    const int aRow = lr + ((lane >> 3) & 1) * 8;
    const int aCol = (lane >> 4) * 8;
    const int kN   = ((lane >> 4) & 1) * 8;
    const int kK   = ((lane >> 3) & 1) * 8;
    const int vRow = lane & 15;
    const int vN   = (lane >> 4) * 8;

    uint32_t qh[4][4], ql[4][4];
    #pragma unroll
    for (int ks = 0; ks < 4; ks++) {
        ldsm_x4(qh[ks][0], qh[ks][1], qh[ks][2], qh[ks][3],
                smem_u32(QsH + (warp * 16 + aRow) * KV_STR + ks * 16 + aCol));
        ldsm_x4(ql[ks][0], ql[ks][1], ql[ks][2], ql[ks][3],
                smem_u32(QsL + (warp * 16 + aRow) * KV_STR + ks * 16 + aCol));
    }

    float O[8][4];
    #pragma unroll
    for (int nt = 0; nt < 8; nt++)
        #pragma unroll
        for (int i = 0; i < 4; i++) O[nt][i] = 0.0f;
    float lsum0 = 0.0f, lsum1 = 0.0f;

    int buf = 0;
    for (int k0 = kstart; k0 <= q0; k0 += 64) {
        if (k0 != kstart) {
            cp_wait0();
            __syncthreads();
        }
        if (k0 + 64 <= q0) load_kv(buf ^ 1, k0 + 64);

        __half* st = asm_ + 2 * AT_BUF + buf * AT_STAGE;
        const __half* KsH = st;
        const __half* VsH = st + AT_BUF;

        float S[8][4];
        #pragma unroll
        for (int nt = 0; nt < 8; nt++)
            #pragma unroll
            for (int i = 0; i < 4; i++) S[nt][i] = 0.0f;

        #pragma unroll
        for (int ks = 0; ks < 4; ks++) {
            #pragma unroll
            for (int np = 0; np < 4; np++) {
                uint32_t b0, b1, b2, b3;
                ldsm_x4(b0, b1, b2, b3,
                        smem_u32(KsH + (np * 16 + kN + lr) * KV_STR + ks * 16 + kK));
                mma16816(S[2*np],   qh[ks][0], qh[ks][1], qh[ks][2], qh[ks][3], b0, b1);
                mma16816(S[2*np+1], qh[ks][0], qh[ks][1], qh[ks][2], qh[ks][3], b2, b3);
                mma16816(S[2*np],   ql[ks][0], ql[ks][1], ql[ks][2], ql[ks][3], b0, b1);
                mma16816(S[2*np+1], ql[ks][0], ql[ks][1], ql[ks][2], ql[ks][3], b2, b3);
            }
        }

        uint32_t PH0[8], PH1[8], PL0[8], PL1[8];
        const float i0f = (float)(q0 + warp * 16 + (lane >> 2) - k0);
        const float i1f = i0f + 8.0f;
        const float jcb = (float)((lane & 3) * 2);
        #pragma unroll
        for (int nt = 0; nt < 8; nt++) {
            const float jc  = (float)(nt * 8) + jcb;
            const float d00 = i0f - jc, d01 = d00 - 1.0f;
            const float d10 = i1f - jc, d11 = d10 - 1.0f;
            const float p00 = (d00 >= 0.0f) ? ex2(fmaf(S[nt][0], qs, -rl * d00)) : 0.0f;
            const float p01 = (d01 >= 0.0f) ? ex2(fmaf(S[nt][1], qs, -rl * d01)) : 0.0f;
            const float p10 = (d10 >= 0.0f) ? ex2(fmaf(S[nt][2], qs, -rl * d10)) : 0.0f;
            const float p11 = (d11 >= 0.0f) ? ex2(fmaf(S[nt][3], qs, -rl * d11)) : 0.0f;
            lsum0 += p00 + p01;
            lsum1 += p10 + p11;
            const __half h00 = __float2half_rn(p00), h01 = __float2half_rn(p01);
            const __half h10 = __float2half_rn(p10), h11 = __float2half_rn(p11);
            __half2 hh0 = __halves2half2(h00, h01);
            __half2 hh1 = __halves2half2(h10, h11);
            PH0[nt] = *reinterpret_cast<uint32_t*>(&hh0);
            PH1[nt] = *reinterpret_cast<uint32_t*>(&hh1);
            PL0[nt] = pack2(p00 - __half2float(h00), p01 - __half2float(h01));
            PL1[nt] = pack2(p10 - __half2float(h10), p11 - __half2float(h11));
        }

        #pragma unroll
        for (int ks = 0; ks < 4; ks++) {
            const uint32_t a0 = PH0[2*ks], a1 = PH1[2*ks], a2 = PH0[2*ks+1], a3 = PH1[2*ks+1];
            const uint32_t e0 = PL0[2*ks], e1 = PL1[2*ks], e2 = PL0[2*ks+1], e3 = PL1[2*ks+1];
            #pragma unroll
            for (int np = 0; np < 4; np++) {
                uint32_t v0, v1, v2, v3;
                ldsm_x4t(v0, v1, v2, v3,
                         smem_u32(VsH + (ks * 16 + vRow) * KV_STR + np * 16 + vN));
                mma16816(O[2*np],   a0, a1, a2, a3, v0, v1);
                mma16816(O[2*np+1], a0, a1, a2, a3, v2, v3);
                mma16816(O[2*np],   e0, e1, e2, e3, v0, v1);
                mma16816(O[2*np+1], e0, e1, e2, e3, v2, v3);
            }
        }
        buf ^= 1;
    }

    lsum0 += __shfl_xor_sync(0xffffffffu, lsum0, 1);
    lsum0 += __shfl_xor_sync(0xffffffffu, lsum0, 2);
    lsum1 += __shfl_xor_sync(0xffffffffu, lsum1, 1);
    lsum1 += __shfl_xor_sync(0xffffffffu, lsum1, 2);
    const float inv0 = 1.0f / lsum0;
    const float inv1 = 1.0f / lsum1;

    const int irow = q0 + warp * 16 + (lane >> 2);
    const size_t rb0 = (rowBase + irow) * CDIM + h * HD;
    const size_t rb1 = rb0 + (size_t)8 * CDIM;
    #pragma unroll
    for (int nt = 0; nt < 8; nt++) {
        const int col = nt * 8 + (lane & 3) * 2;
        const float y0 = O[nt][0] * inv0, y1 = O[nt][1] * inv0;
        const float y2 = O[nt][2] * inv1, y3 = O[nt][3] * inv1;
        const __half a0 = __float2half_rn(y0), a1 = __float2half_rn(y1);
        const __half a2 = __float2half_rn(y2), a3 = __float2half_rn(y3);
        *(__half2*)(yhi + rb0 + col) = __halves2half2(a0, a1);
        *(__half2*)(yhi + rb1 + col) = __halves2half2(a2, a3);
        *(__half2*)(ylo + rb0 + col) = __halves2half2(
            __float2half_rn(y0 - __half2float(a0)), __float2half_rn(y1 - __half2float(a1)));
        *(__half2*)(ylo + rb1 + col) = __halves2half2(
            __float2half_rn(y2 - __half2float(a2)), __float2half_rn(y3 - __half2float(a3)));
    }
}

// ---------------------------------------------------------------------------
extern "C" void kernel_launch(void* const* d_in, const int* in_sizes, int n_in,
                              void* d_out, int out_size)
{
    const float* x      = (const float*)d_in[0];
    const float* W_attn = (const float*)d_in[1];
    const float* b_attn = (const float*)d_in[2];
    const float* W_proj = (const float*)d_in[3];
    const float* b_proj = (const float*)d_in[4];
    const float* decay  = (const float*)d_in[5];
    float* out = (float*)d_out;

    __half *qkhi, *qklo, *xhi, *xlo, *wahi, *wphi, *yhi, *ylo;
    cudaGetSymbolAddress((void**)&qkhi, g_qkhi);
    cudaGetSymbolAddress((void**)&qklo, g_qklo);
    cudaGetSymbolAddress((void**)&xhi,  g_xhi);
    cudaGetSymbolAddress((void**)&xlo,  g_xlo);
    cudaGetSymbolAddress((void**)&wahi, g_wahi);
    cudaGetSymbolAddress((void**)&wphi, g_wphi);
    cudaGetSymbolAddress((void**)&yhi,  g_yhi);
    cudaGetSymbolAddress((void**)&ylo,  g_ylo);

    static bool attr_set = false;
    if (!attr_set) {
        cudaFuncSetAttribute((const void*)hgemm_split<true>,
                             cudaFuncAttributeMaxDynamicSharedMemorySize, HG_SMEM);
        cudaFuncSetAttribute((const void*)hgemm_split<false>,
                             cudaFuncAttributeMaxDynamicSharedMemorySize, HG_SMEM);
        cudaFuncSetAttribute((const void*)attn_mma,
                             cudaFuncAttributeMaxDynamicSharedMemorySize, AT_SMEM);
        attr_set = true;
    }

    // 0) x: hi/lo split; weights: hi-only convert
    {
        int n4 = MROWS * CDIM / 4;
        split_fp32<<<(n4 + 255) / 256, 256>>>((const float4*)x, (__half2*)xhi, (__half2*)xlo, n4);
        n4 = CDIM * C3 / 4;
        cvt_fp16<<<(n4 + 255) / 256, 256>>>((const float4*)W_attn, (__half2*)wahi, n4);
        n4 = CDIM * CDIM / 4;
        cvt_fp16<<<(n4 + 255) / 256, 256>>>((const float4*)W_proj, (__half2*)wphi, n4);
    }
    // 1) qkv = x @ W_attn + b_attn -> fp16 hi (+lo for Q cols)
    {
        dim3 grid(C3 / 128, MROWS / 128);
        hgemm_split<true><<<grid, 256, HG_SMEM>>>(
            xhi, xlo, wahi, b_attn, nullptr, qkhi, qklo, C3, CDIM);
    }
    // 2) fused decay attention -> yhi/ylo
    {
        dim3 grid(SEQ / 64, NHEAD, BATCH);
        attn_mma<<<grid, 128, AT_SMEM>>>(qkhi, qklo, decay, yhi, ylo);
    }
    // 3) out = y @ W_proj + b_proj -> fp32
    {
        dim3 grid(CDIM / 128, MROWS / 128);
        hgemm_split<false><<<grid, 256, HG_SMEM>>>(
            yhi, ylo, wphi, b_proj, out, nullptr, nullptr, CDIM, CDIM);
    }
}

// round 14
// speedup vs baseline: 1.0932x; 1.0556x over previous
#include <cuda_runtime.h>
#include <cuda_fp16.h>
#include <cstdint>

// Problem constants (fixed by setup_inputs)
#define BATCH 4
#define SEQ   2048
#define CDIM  768
#define NHEAD 12
#define HD    64
#define MROWS (BATCH*SEQ)      // 8192
#define C3    (3*CDIM)         // 2304
#define LOG2E 1.4426950408889634f

// Scratch (device globals; no runtime allocation)
__device__ __half g_qkhi[(size_t)MROWS * C3];
__device__ __half g_qklo[(size_t)MROWS * C3];    // only Q section written/read
__device__ __half g_xhi[(size_t)MROWS * CDIM];
__device__ __half g_xlo[(size_t)MROWS * CDIM];
__device__ __half g_wahi[(size_t)CDIM * C3];     // weights: hi only (split-2)
__device__ __half g_wphi[(size_t)CDIM * CDIM];
__device__ __half g_yhi[(size_t)MROWS * CDIM];
__device__ __half g_ylo[(size_t)MROWS * CDIM];

__device__ __forceinline__ float ex2(float x) {
    float y;
    asm("ex2.approx.f32 %0, %1;" : "=f"(y) : "f"(x));
    return y;
}
__device__ __forceinline__ uint32_t smem_u32(const void* p) {
    return (uint32_t)__cvta_generic_to_shared(p);
}
__device__ __forceinline__ void cp16(uint32_t dst, const void* src) {
    asm volatile("cp.async.ca.shared.global [%0], [%1], 16;\n" :: "r"(dst), "l"(src));
}
__device__ __forceinline__ void cp_commit() {
    asm volatile("cp.async.commit_group;\n" ::: "memory");
}
__device__ __forceinline__ void cp_wait0() {
    asm volatile("cp.async.wait_group 0;\n" ::: "memory");
}
__device__ __forceinline__ void ldsm_x4(uint32_t& r0, uint32_t& r1, uint32_t& r2, uint32_t& r3,
                                        uint32_t addr) {
    asm volatile("ldmatrix.sync.aligned.m8n8.x4.shared.b16 {%0,%1,%2,%3}, [%4];"
                 : "=r"(r0), "=r"(r1), "=r"(r2), "=r"(r3) : "r"(addr));
}
__device__ __forceinline__ void ldsm_x4t(uint32_t& r0, uint32_t& r1, uint32_t& r2, uint32_t& r3,
                                         uint32_t addr) {
    asm volatile("ldmatrix.sync.aligned.m8n8.x4.trans.shared.b16 {%0,%1,%2,%3}, [%4];"
                 : "=r"(r0), "=r"(r1), "=r"(r2), "=r"(r3) : "r"(addr));
}
__device__ __forceinline__ void mma16816(float* c,
                                         uint32_t a0, uint32_t a1, uint32_t a2, uint32_t a3,
                                         uint32_t b0, uint32_t b1) {
    asm volatile("mma.sync.aligned.m16n8k16.row.col.f32.f16.f16.f32 "
                 "{%0,%1,%2,%3}, {%4,%5,%6,%7}, {%8,%9}, {%0,%1,%2,%3};"
                 : "+f"(c[0]), "+f"(c[1]), "+f"(c[2]), "+f"(c[3])
                 : "r"(a0), "r"(a1), "r"(a2), "r"(a3), "r"(b0), "r"(b1));
}
__device__ __forceinline__ uint32_t pack2(float a, float b) {
    __half2 h = __halves2half2(__float2half_rn(a), __float2half_rn(b));
    return *reinterpret_cast<uint32_t*>(&h);
}

// ---------------------------------------------------------------------------
// fp32 -> (fp16 hi, fp16 lo) split, vectorized by 4. (A operands)
// ---------------------------------------------------------------------------
__global__ void __launch_bounds__(256) split_fp32(
    const float4* __restrict__ src, __half2* __restrict__ hi,
    __half2* __restrict__ lo, int n4)
{
    const int i = blockIdx.x * blockDim.x + threadIdx.x;
    if (i >= n4) return;
    float4 v = src[i];
    __half h0 = __float2half_rn(v.x), h1 = __float2half_rn(v.y);
    __half h2 = __float2half_rn(v.z), h3 = __float2half_rn(v.w);
    hi[2*i]   = __halves2half2(h0, h1);
    hi[2*i+1] = __halves2half2(h2, h3);
    lo[2*i]   = __halves2half2(__float2half_rn(v.x - __half2float(h0)),
                               __float2half_rn(v.y - __half2float(h1)));
    lo[2*i+1] = __halves2half2(__float2half_rn(v.z - __half2float(h2)),
                               __float2half_rn(v.w - __half2float(h3)));
}

// fp32 -> fp16 convert only (B operands: hi part only)
__global__ void __launch_bounds__(256) cvt_fp16(
    const float4* __restrict__ src, __half2* __restrict__ hi, int n4)
{
    const int i = blockIdx.x * blockDim.x + threadIdx.x;
    if (i >= n4) return;
    float4 v = src[i];
    hi[2*i]   = __halves2half2(__float2half_rn(v.x), __float2half_rn(v.y));
    hi[2*i+1] = __halves2half2(__float2half_rn(v.z), __float2half_rn(v.w));
}

// ---------------------------------------------------------------------------
// Split-2 fp16 tensor-core GEMM + bias, cp.async double-buffered, BK=32.
//   C = (Ahi+Alo) @ Bhi + bias
// Warp grid 4x2 (warp tile 32x64): minimizes smem LDSM traffic
//   (A re-read 2x, B re-read 4x -> 32KB/k16/CTA vs 40KB for 2x4 grid).
// B fragments via ldsm.x4t (proven V-operand pattern).
// OUT_HALF: write hi/lo fp16 (lo only for Q columns c<CDIM). Else fp32.
// BM=128, BK=32, 256 threads = 8 warps.
// ---------------------------------------------------------------------------
#define BK    32
#define A_STR 40
#define B_STR 136
#define HG_ABUF (128 * A_STR)
#define HG_BBUF (BK * B_STR)
#define HG_STAGE (2 * HG_ABUF + HG_BBUF)         // halves
#define HG_SMEM  (2 * HG_STAGE * 2)              // bytes (~58 KB)

template<bool OUT_HALF>
__global__ void __launch_bounds__(256, 2) hgemm_split(
    const __half* __restrict__ Ahi, const __half* __restrict__ Alo,
    const __half* __restrict__ Bhi,
    const float* __restrict__ bias, float* __restrict__ C,
    __half* __restrict__ Chi, __half* __restrict__ Clo,
    int N, int K)
{
    extern __shared__ __align__(16) __half hsm[];

    const int t    = threadIdx.x;
    const int warp = t >> 5;
    const int lane = t & 31;
    const int wm   = (warp >> 1) * 32;    // 4 m-stripes
    const int wn   = (warp & 1) * 64;     // 2 n-stripes

    const size_t aG   = (size_t)blockIdx.y * 128 * K;
    const int    bCol = blockIdx.x * 128;

    const int g     = lane >> 3;
    const int lr    = lane & 7;
    const int aRowF = (g & 1) * 8 + lr;   // A frag row within m16
    const int aColF = (g >> 1) * 8;       // A frag k offset
    const int bRowT = lane & 15;          // B x4t: k row within 16
    const int bNT   = (lane >> 4) * 8;    // B x4t: n offset

    float acc[2][8][4];
    #pragma unroll
    for (int mt = 0; mt < 2; mt++)
        #pragma unroll
        for (int nt = 0; nt < 8; nt++)
            #pragma unroll
            for (int i = 0; i < 4; i++) acc[mt][nt][i] = 0.0f;

    auto load_tile = [&](int s, int ko) {
        __half* base = hsm + s * HG_STAGE;
        __half* aH = base;
        __half* aL = base + HG_ABUF;
        __half* bH = base + 2 * HG_ABUF;
        #pragma unroll
        for (int it = 0; it < 2; it++) {
            const int u   = it * 256 + t;
            const int row = u >> 2;
            const int c   = (u & 3) * 8;
            const size_t gsrc = aG + (size_t)row * K + ko + c;
            cp16(smem_u32(aH + row * A_STR + c), Ahi + gsrc);
            cp16(smem_u32(aL + row * A_STR + c), Alo + gsrc);
        }
        #pragma unroll
        for (int it = 0; it < 2; it++) {
            const int u   = it * 256 + t;
            const int row = u >> 4;
            const int c   = (u & 15) * 8;
            cp16(smem_u32(bH + row * B_STR + c), Bhi + (size_t)(ko + row) * N + bCol + c);
        }
        cp_commit();
    };

    load_tile(0, 0);
    cp_wait0();
    __syncthreads();

    const int nk = K / BK;
    int buf = 0;
    for (int kt = 0; kt < nk; kt++) {
        if (kt + 1 < nk) load_tile(buf ^ 1, (kt + 1) * BK);

        const __half* base = hsm + buf * HG_STAGE;
        const __half* aH = base;
        const __half* aL = base + HG_ABUF;
        const __half* bH = base + 2 * HG_ABUF;

        #pragma unroll
        for (int ks = 0; ks < 2; ks++) {
            uint32_t afh[2][4], afl[2][4], bf[8][2];
            #pragma unroll
            for (int mt = 0; mt < 2; mt++) {
                const int row = wm + mt * 16 + aRowF;
                ldsm_x4(afh[mt][0], afh[mt][1], afh[mt][2], afh[mt][3],
                        smem_u32(aH + row * A_STR + ks * 16 + aColF));
                ldsm_x4(afl[mt][0], afl[mt][1], afl[mt][2], afl[mt][3],
                        smem_u32(aL + row * A_STR + ks * 16 + aColF));
            }
            #pragma unroll
            for (int p = 0; p < 4; p++) {   // n-tile pairs (2p, 2p+1)
                ldsm_x4t(bf[2*p][0], bf[2*p][1], bf[2*p+1][0], bf[2*p+1][1],
                         smem_u32(bH + (ks * 16 + bRowT) * B_STR + wn + p * 16 + bNT));
            }
            #pragma unroll
            for (int mt = 0; mt < 2; mt++)
                #pragma unroll
                for (int nt = 0; nt < 8; nt++) {
                    mma16816(acc[mt][nt], afh[mt][0], afh[mt][1], afh[mt][2], afh[mt][3],
                             bf[nt][0], bf[nt][1]);
                    mma16816(acc[mt][nt], afl[mt][0], afl[mt][1], afl[mt][2], afl[mt][3],
                             bf[nt][0], bf[nt][1]);
                }
        }

        if (kt + 1 < nk) {
            cp_wait0();
            __syncthreads();
            buf ^= 1;
        }
    }

    #pragma unroll
    for (int mt = 0; mt < 2; mt++) {
        const int r0 = blockIdx.y * 128 + wm + mt * 16 + (lane >> 2);
        #pragma unroll
        for (int nt = 0; nt < 8; nt++) {
            const int c0 = bCol + wn + nt * 8 + (lane & 3) * 2;
            const float b0 = bias[c0], b1 = bias[c0 + 1];
            const float v00 = acc[mt][nt][0] + b0, v01 = acc[mt][nt][1] + b1;
            const float v10 = acc[mt][nt][2] + b0, v11 = acc[mt][nt][3] + b1;
            if (OUT_HALF) {
                const __half h00 = __float2half_rn(v00), h01 = __float2half_rn(v01);
                const __half h10 = __float2half_rn(v10), h11 = __float2half_rn(v11);
                *(__half2*)(Chi + (size_t)r0 * N + c0)       = __halves2half2(h00, h01);
                *(__half2*)(Chi + (size_t)(r0 + 8) * N + c0) = __halves2half2(h10, h11);
                if (c0 < CDIM) {   // lo only consumed for Q columns
                    *(__half2*)(Clo + (size_t)r0 * N + c0)       = __halves2half2(
                        __float2half_rn(v00 - __half2float(h00)),
                        __float2half_rn(v01 - __half2float(h01)));
                    *(__half2*)(Clo + (size_t)(r0 + 8) * N + c0) = __halves2half2(
                        __float2half_rn(v10 - __half2float(h10)),
                        __float2half_rn(v11 - __half2float(h11)));
                }
            } else {
                *(float2*)(C + (size_t)r0 * N + c0)       = make_float2(v00, v01);
                *(float2*)(C + (size_t)(r0 + 8) * N + c0) = make_float2(v10, v11);
            }
        }
    }
}

// ---------------------------------------------------------------------------
// Tensor-core flash attention, split-2 (unchanged from R13 best):
//   S = (Qhi+Qlo)@Khi^T, P = exp2(S*qs - rl*dist), O = (Phi+Plo)@Vhi.
// 3 CTAs/SM. Window 14/r.
// ---------------------------------------------------------------------------
#define KV_STR 72
#define AT_BUF (64 * KV_STR)
#define AT_STAGE (2 * AT_BUF)                 // K hi, V hi
#define AT_SMEM ((2 * AT_BUF + 2 * AT_STAGE) * 2)   // bytes (~55 KB)

__device__ __forceinline__ void ldsm_x4_a(uint32_t& r0, uint32_t& r1, uint32_t& r2, uint32_t& r3,
                                          uint32_t addr) {
    asm volatile("ldmatrix.sync.aligned.m8n8.x4.shared.b16 {%0,%1,%2,%3}, [%4];"
                 : "=r"(r0), "=r"(r1), "=r"(r2), "=r"(r3) : "r"(addr));
}

__global__ void __launch_bounds__(128, 3) attn_mma(
    const __half* __restrict__ qkhi, const __half* __restrict__ qklo,
    const float* __restrict__ decay,
    __half* __restrict__ yhi, __half* __restrict__ ylo)
{
    extern __shared__ __align__(16) __half asm_[];
    __half* QsH = asm_;
    __half* QsL = asm_ + AT_BUF;

    const int q0   = blockIdx.x * 64;
    const int h    = blockIdx.y;
    const int bb   = blockIdx.z;
    const int t    = threadIdx.x;
    const int warp = t >> 5;
    const int lane = t & 31;

    const size_t rowBase = (size_t)bb * SEQ;
    const float r  = decay[h];
    const float rl = r * LOG2E;
    const float qs = 0.125f * LOG2E;

    {
        #pragma unroll
        for (int it = 0; it < 4; it++) {
            const int u = it * 128 + t;
            const int row = u >> 3;
            const int c = (u & 7) * 8;
            const size_t gsrc = (rowBase + q0 + row) * C3 + h * HD + c;
            cp16(smem_u32(QsH + row * KV_STR + c), qkhi + gsrc);
            cp16(smem_u32(QsL + row * KV_STR + c), qklo + gsrc);
        }
        cp_commit();
    }

    auto load_kv = [&](int s, int k0) {
        __half* st = asm_ + 2 * AT_BUF + s * AT_STAGE;
        __half* kH = st;
        __half* vH = st + AT_BUF;
        #pragma unroll
        for (int it = 0; it < 4; it++) {
            const int u = it * 128 + t;
            const int row = u >> 3;
            const int c = (u & 7) * 8;
            const size_t gk = (rowBase + k0 + row) * C3 + CDIM + h * HD + c;
            cp16(smem_u32(kH + row * KV_STR + c), qkhi + gk);
            cp16(smem_u32(vH + row * KV_STR + c), qkhi + gk + CDIM);
        }
        cp_commit();
    };

    const int W = (r > 1e-6f) ? (int)(14.0f / r) : (1 << 30);
    int km = q0 - W;
    if (km < 0) km = 0;
    const int kstart = (km / 64) * 64;

    load_kv(0, kstart);
    cp_wait0();
    __syncthreads();

    const int lr   = lane & 7;
    const int aRow = lr + ((lane >> 3) & 1) * 8;
    const int aCol = (lane >> 4) * 8;
    const int kN   = ((lane >> 4) & 1) * 8;
    const int kK   = ((lane >> 3) & 1) * 8;
    const int vRow = lane & 15;
    const int vN   = (lane >> 4) * 8;

    uint32_t qh[4][4], ql[4][4];
    #pragma unroll
    for (int ks = 0; ks < 4; ks++) {
        ldsm_x4_a(qh[ks][0], qh[ks][1], qh[ks][2], qh[ks][3],
                  smem_u32(QsH + (warp * 16 + aRow) * KV_STR + ks * 16 + aCol));
        ldsm_x4_a(ql[ks][0], ql[ks][1], ql[ks][2], ql[ks][3],
                  smem_u32(QsL + (warp * 16 + aRow) * KV_STR + ks * 16 + aCol));
    }

    float O[8][4];
    #pragma unroll
    for (int nt = 0; nt < 8; nt++)
        #pragma unroll
        for (int i = 0; i < 4; i++) O[nt][i] = 0.0f;
    float lsum0 = 0.0f, lsum1 = 0.0f;

    int buf = 0;
    for (int k0 = kstart; k0 <= q0; k0 += 64) {
        if (k0 != kstart) {
            cp_wait0();
            __syncthreads();
        }
        if (k0 + 64 <= q0) load_kv(buf ^ 1, k0 + 64);

        __half* st = asm_ + 2 * AT_BUF + buf * AT_STAGE;
        const __half* KsH = st;
        const __half* VsH = st + AT_BUF;

        float S[8][4];
        #pragma unroll
        for (int nt = 0; nt < 8; nt++)
            #pragma unroll
            for (int i = 0; i < 4; i++) S[nt][i] = 0.0f;

        #pragma unroll
        for (int ks = 0; ks < 4; ks++) {
            #pragma unroll
            for (int np = 0; np < 4; np++) {
                uint32_t b0, b1, b2, b3;
                ldsm_x4_a(b0, b1, b2, b3,
                          smem_u32(KsH + (np * 16 + kN + lr) * KV_STR + ks * 16 + kK));
                mma16816(S[2*np],   qh[ks][0], qh[ks][1], qh[ks][2], qh[ks][3], b0, b1);
                mma16816(S[2*np+1], qh[ks][0], qh[ks][1], qh[ks][2], qh[ks][3], b2, b3);
                mma16816(S[2*np],   ql[ks][0], ql[ks][1], ql[ks][2], ql[ks][3], b0, b1);
                mma16816(S[2*np+1], ql[ks][0], ql[ks][1], ql[ks][2], ql[ks][3], b2, b3);
            }
        }

        uint32_t PH0[8], PH1[8], PL0[8], PL1[8];
        const float i0f = (float)(q0 + warp * 16 + (lane >> 2) - k0);
        const float i1f = i0f + 8.0f;
        const float jcb = (float)((lane & 3) * 2);
        #pragma unroll
        for (int nt = 0; nt < 8; nt++) {
            const float jc  = (float)(nt * 8) + jcb;
            const float d00 = i0f - jc, d01 = d00 - 1.0f;
            const float d10 = i1f - jc, d11 = d10 - 1.0f;
            const float p00 = (d00 >= 0.0f) ? ex2(fmaf(S[nt][0], qs, -rl * d00)) : 0.0f;
            const float p01 = (d01 >= 0.0f) ? ex2(fmaf(S[nt][1], qs, -rl * d01)) : 0.0f;
            const float p10 = (d10 >= 0.0f) ? ex2(fmaf(S[nt][2], qs, -rl * d10)) : 0.0f;
            const float p11 = (d11 >= 0.0f) ? ex2(fmaf(S[nt][3], qs, -rl * d11)) : 0.0f;
            lsum0 += p00 + p01;
            lsum1 += p10 + p11;
            const __half h00 = __float2half_rn(p00), h01 = __float2half_rn(p01);
            const __half h10 = __float2half_rn(p10), h11 = __float2half_rn(p11);
            __half2 hh0 = __halves2half2(h00, h01);
            __half2 hh1 = __halves2half2(h10, h11);
            PH0[nt] = *reinterpret_cast<uint32_t*>(&hh0);
            PH1[nt] = *reinterpret_cast<uint32_t*>(&hh1);
            PL0[nt] = pack2(p00 - __half2float(h00), p01 - __half2float(h01));
            PL1[nt] = pack2(p10 - __half2float(h10), p11 - __half2float(h11));
        }

        #pragma unroll
        for (int ks = 0; ks < 4; ks++) {
            const uint32_t a0 = PH0[2*ks], a1 = PH1[2*ks], a2 = PH0[2*ks+1], a3 = PH1[2*ks+1];
            const uint32_t e0 = PL0[2*ks], e1 = PL1[2*ks], e2 = PL0[2*ks+1], e3 = PL1[2*ks+1];
            #pragma unroll
            for (int np = 0; np < 4; np++) {
                uint32_t v0, v1, v2, v3;
                ldsm_x4t(v0, v1, v2, v3,
                         smem_u32(VsH + (ks * 16 + vRow) * KV_STR + np * 16 + vN));
                mma16816(O[2*np],   a0, a1, a2, a3, v0, v1);
                mma16816(O[2*np+1], a0, a1, a2, a3, v2, v3);
                mma16816(O[2*np],   e0, e1, e2, e3, v0, v1);
                mma16816(O[2*np+1], e0, e1, e2, e3, v2, v3);
            }
        }
        buf ^= 1;
    }

    lsum0 += __shfl_xor_sync(0xffffffffu, lsum0, 1);
    lsum0 += __shfl_xor_sync(0xffffffffu, lsum0, 2);
    lsum1 += __shfl_xor_sync(0xffffffffu, lsum1, 1);
    lsum1 += __shfl_xor_sync(0xffffffffu, lsum1, 2);
    const float inv0 = 1.0f / lsum0;
    const float inv1 = 1.0f / lsum1;

    const int irow = q0 + warp * 16 + (lane >> 2);
    const size_t rb0 = (rowBase + irow) * CDIM + h * HD;
    const size_t rb1 = rb0 + (size_t)8 * CDIM;
    #pragma unroll
    for (int nt = 0; nt < 8; nt++) {
        const int col = nt * 8 + (lane & 3) * 2;
        const float y0 = O[nt][0] * inv0, y1 = O[nt][1] * inv0;
        const float y2 = O[nt][2] * inv1, y3 = O[nt][3] * inv1;
        const __half a0 = __float2half_rn(y0), a1 = __float2half_rn(y1);
        const __half a2 = __float2half_rn(y2), a3 = __float2half_rn(y3);
        *(__half2*)(yhi + rb0 + col) = __halves2half2(a0, a1);
        *(__half2*)(yhi + rb1 + col) = __halves2half2(a2, a3);
        *(__half2*)(ylo + rb0 + col) = __halves2half2(
            __float2half_rn(y0 - __half2float(a0)), __float2half_rn(y1 - __half2float(a1)));
        *(__half2*)(ylo + rb1 + col) = __halves2half2(
            __float2half_rn(y2 - __half2float(a2)), __float2half_rn(y3 - __half2float(a3)));
    }
}

// ---------------------------------------------------------------------------
extern "C" void kernel_launch(void* const* d_in, const int* in_sizes, int n_in,
                              void* d_out, int out_size)
{
    const float* x      = (const float*)d_in[0];
    const float* W_attn = (const float*)d_in[1];
    const float* b_attn = (const float*)d_in[2];
    const float* W_proj = (const float*)d_in[3];
    const float* b_proj = (const float*)d_in[4];
    const float* decay  = (const float*)d_in[5];
    float* out = (float*)d_out;

    __half *qkhi, *qklo, *xhi, *xlo, *wahi, *wphi, *yhi, *ylo;
    cudaGetSymbolAddress((void**)&qkhi, g_qkhi);
    cudaGetSymbolAddress((void**)&qklo, g_qklo);
    cudaGetSymbolAddress((void**)&xhi,  g_xhi);
    cudaGetSymbolAddress((void**)&xlo,  g_xlo);
    cudaGetSymbolAddress((void**)&wahi, g_wahi);
    cudaGetSymbolAddress((void**)&wphi, g_wphi);
    cudaGetSymbolAddress((void**)&yhi,  g_yhi);
    cudaGetSymbolAddress((void**)&ylo,  g_ylo);

    static bool attr_set = false;
    if (!attr_set) {
        cudaFuncSetAttribute((const void*)hgemm_split<true>,
                             cudaFuncAttributeMaxDynamicSharedMemorySize, HG_SMEM);
        cudaFuncSetAttribute((const void*)hgemm_split<false>,
                             cudaFuncAttributeMaxDynamicSharedMemorySize, HG_SMEM);
        cudaFuncSetAttribute((const void*)attn_mma,
                             cudaFuncAttributeMaxDynamicSharedMemorySize, AT_SMEM);
        attr_set = true;
    }

    // 0) x: hi/lo split; weights: hi-only convert
    {
        int n4 = MROWS * CDIM / 4;
        split_fp32<<<(n4 + 255) / 256, 256>>>((const float4*)x, (__half2*)xhi, (__half2*)xlo, n4);
        n4 = CDIM * C3 / 4;
        cvt_fp16<<<(n4 + 255) / 256, 256>>>((const float4*)W_attn, (__half2*)wahi, n4);
        n4 = CDIM * CDIM / 4;
        cvt_fp16<<<(n4 + 255) / 256, 256>>>((const float4*)W_proj, (__half2*)wphi, n4);
    }
    // 1) qkv = x @ W_attn + b_attn -> fp16 hi (+lo for Q cols)
    {
        dim3 grid(C3 / 128, MROWS / 128);
        hgemm_split<true><<<grid, 256, HG_SMEM>>>(
            xhi, xlo, wahi, b_attn, nullptr, qkhi, qklo, C3, CDIM);
    }
    // 2) fused decay attention -> yhi/ylo
    {
        dim3 grid(SEQ / 64, NHEAD, BATCH);
        attn_mma<<<grid, 128, AT_SMEM>>>(qkhi, qklo, decay, yhi, ylo);
    }
    // 3) out = y @ W_proj + b_proj -> fp32
    {
        dim3 grid(CDIM / 128, MROWS / 128);
        hgemm_split<false><<<grid, 256, HG_SMEM>>>(
            yhi, ylo, wphi, b_proj, out, nullptr, nullptr, CDIM, CDIM);
    }
}

// round 15
// speedup vs baseline: 1.1262x; 1.0302x over previous
#include <cuda_runtime.h>
#include <cuda_fp16.h>
#include <cstdint>

// Problem constants (fixed by setup_inputs)
#define BATCH 4
#define SEQ   2048
#define CDIM  768
#define NHEAD 12
#define HD    64
#define MROWS (BATCH*SEQ)      // 8192
#define C3    (3*CDIM)         // 2304
#define LOG2E 1.4426950408889634f

// Scratch (device globals; no runtime allocation)
__device__ __half g_qkhi[(size_t)MROWS * C3];
__device__ __half g_qklo[(size_t)MROWS * C3];    // only Q section written/read
__device__ __half g_xhi[(size_t)MROWS * CDIM];
__device__ __half g_xlo[(size_t)MROWS * CDIM];
__device__ __half g_wahi[(size_t)CDIM * C3];     // weights: hi only (split-2)
__device__ __half g_wphi[(size_t)CDIM * CDIM];
__device__ __half g_yhi[(size_t)MROWS * CDIM];
__device__ __half g_ylo[(size_t)MROWS * CDIM];

__device__ __forceinline__ float ex2(float x) {
    float y;
    asm("ex2.approx.f32 %0, %1;" : "=f"(y) : "f"(x));
    return y;
}
__device__ __forceinline__ uint32_t smem_u32(const void* p) {
    return (uint32_t)__cvta_generic_to_shared(p);
}
__device__ __forceinline__ void cp16(uint32_t dst, const void* src) {
    asm volatile("cp.async.ca.shared.global [%0], [%1], 16;\n" :: "r"(dst), "l"(src));
}
__device__ __forceinline__ void cp_commit() {
    asm volatile("cp.async.commit_group;\n" ::: "memory");
}
__device__ __forceinline__ void cp_wait0() {
    asm volatile("cp.async.wait_group 0;\n" ::: "memory");
}
__device__ __forceinline__ void ldsm_x4(uint32_t& r0, uint32_t& r1, uint32_t& r2, uint32_t& r3,
                                        uint32_t addr) {
    asm volatile("ldmatrix.sync.aligned.m8n8.x4.shared.b16 {%0,%1,%2,%3}, [%4];"
                 : "=r"(r0), "=r"(r1), "=r"(r2), "=r"(r3) : "r"(addr));
}
__device__ __forceinline__ void ldsm_x4t(uint32_t& r0, uint32_t& r1, uint32_t& r2, uint32_t& r3,
                                         uint32_t addr) {
    asm volatile("ldmatrix.sync.aligned.m8n8.x4.trans.shared.b16 {%0,%1,%2,%3}, [%4];"
                 : "=r"(r0), "=r"(r1), "=r"(r2), "=r"(r3) : "r"(addr));
}
__device__ __forceinline__ void mma16816(float* c,
                                         uint32_t a0, uint32_t a1, uint32_t a2, uint32_t a3,
                                         uint32_t b0, uint32_t b1) {
    asm volatile("mma.sync.aligned.m16n8k16.row.col.f32.f16.f16.f32 "
                 "{%0,%1,%2,%3}, {%4,%5,%6,%7}, {%8,%9}, {%0,%1,%2,%3};"
                 : "+f"(c[0]), "+f"(c[1]), "+f"(c[2]), "+f"(c[3])
                 : "r"(a0), "r"(a1), "r"(a2), "r"(a3), "r"(b0), "r"(b1));
}

// ---------------------------------------------------------------------------
// fp32 -> (fp16 hi, fp16 lo) split, vectorized by 4. (A operands)
// ---------------------------------------------------------------------------
__global__ void __launch_bounds__(256) split_fp32(
    const float4* __restrict__ src, __half2* __restrict__ hi,
    __half2* __restrict__ lo, int n4)
{
    const int i = blockIdx.x * blockDim.x + threadIdx.x;
    if (i >= n4) return;
    float4 v = src[i];
    __half h0 = __float2half_rn(v.x), h1 = __float2half_rn(v.y);
    __half h2 = __float2half_rn(v.z), h3 = __float2half_rn(v.w);
    hi[2*i]   = __halves2half2(h0, h1);
    hi[2*i+1] = __halves2half2(h2, h3);
    lo[2*i]   = __halves2half2(__float2half_rn(v.x - __half2float(h0)),
                               __float2half_rn(v.y - __half2float(h1)));
    lo[2*i+1] = __halves2half2(__float2half_rn(v.z - __half2float(h2)),
                               __float2half_rn(v.w - __half2float(h3)));
}

// fp32 -> fp16 convert only (B operands: hi part only)
__global__ void __launch_bounds__(256) cvt_fp16(
    const float4* __restrict__ src, __half2* __restrict__ hi, int n4)
{
    const int i = blockIdx.x * blockDim.x + threadIdx.x;
    if (i >= n4) return;
    float4 v = src[i];
    hi[2*i]   = __halves2half2(__float2half_rn(v.x), __float2half_rn(v.y));
    hi[2*i+1] = __halves2half2(__float2half_rn(v.z), __float2half_rn(v.w));
}

// ---------------------------------------------------------------------------
// Split-2 fp16 tensor-core GEMM + bias, cp.async double-buffered, BK=32.
//   C = (Ahi+Alo) @ Bhi + bias
// Warp grid 4x2 (warp tile 32x64): measured-best (R14: 152.8us, tensor 62.5%).
// OUT_HALF: write hi/lo fp16 (lo only for Q columns c<CDIM). Else fp32.
// ---------------------------------------------------------------------------
#define BK    32
#define A_STR 40
#define B_STR 136
#define HG_ABUF (128 * A_STR)
#define HG_BBUF (BK * B_STR)
#define HG_STAGE (2 * HG_ABUF + HG_BBUF)         // halves
#define HG_SMEM  (2 * HG_STAGE * 2)              // bytes (~58 KB)

template<bool OUT_HALF>
__global__ void __launch_bounds__(256, 2) hgemm_split(
    const __half* __restrict__ Ahi, const __half* __restrict__ Alo,
    const __half* __restrict__ Bhi,
    const float* __restrict__ bias, float* __restrict__ C,
    __half* __restrict__ Chi, __half* __restrict__ Clo,
    int N, int K)
{
    extern __shared__ __align__(16) __half hsm[];

    const int t    = threadIdx.x;
    const int warp = t >> 5;
    const int lane = t & 31;
    const int wm   = (warp >> 1) * 32;    // 4 m-stripes
    const int wn   = (warp & 1) * 64;     // 2 n-stripes

    const size_t aG   = (size_t)blockIdx.y * 128 * K;
    const int    bCol = blockIdx.x * 128;

    const int g     = lane >> 3;
    const int lr    = lane & 7;
    const int aRowF = (g & 1) * 8 + lr;
    const int aColF = (g >> 1) * 8;
    const int bRowT = lane & 15;
    const int bNT   = (lane >> 4) * 8;

    float acc[2][8][4];
    #pragma unroll
    for (int mt = 0; mt < 2; mt++)
        #pragma unroll
        for (int nt = 0; nt < 8; nt++)
            #pragma unroll
            for (int i = 0; i < 4; i++) acc[mt][nt][i] = 0.0f;

    auto load_tile = [&](int s, int ko) {
        __half* base = hsm + s * HG_STAGE;
        __half* aH = base;
        __half* aL = base + HG_ABUF;
        __half* bH = base + 2 * HG_ABUF;
        #pragma unroll
        for (int it = 0; it < 2; it++) {
            const int u   = it * 256 + t;
            const int row = u >> 2;
            const int c   = (u & 3) * 8;
            const size_t gsrc = aG + (size_t)row * K + ko + c;
            cp16(smem_u32(aH + row * A_STR + c), Ahi + gsrc);
            cp16(smem_u32(aL + row * A_STR + c), Alo + gsrc);
        }
        #pragma unroll
        for (int it = 0; it < 2; it++) {
            const int u   = it * 256 + t;
            const int row = u >> 4;
            const int c   = (u & 15) * 8;
            cp16(smem_u32(bH + row * B_STR + c), Bhi + (size_t)(ko + row) * N + bCol + c);
        }
        cp_commit();
    };

    load_tile(0, 0);
    cp_wait0();
    __syncthreads();

    const int nk = K / BK;
    int buf = 0;
    for (int kt = 0; kt < nk; kt++) {
        if (kt + 1 < nk) load_tile(buf ^ 1, (kt + 1) * BK);

        const __half* base = hsm + buf * HG_STAGE;
        const __half* aH = base;
        const __half* aL = base + HG_ABUF;
        const __half* bH = base + 2 * HG_ABUF;

        #pragma unroll
        for (int ks = 0; ks < 2; ks++) {
            uint32_t afh[2][4], afl[2][4], bf[8][2];
            #pragma unroll
            for (int mt = 0; mt < 2; mt++) {
                const int row = wm + mt * 16 + aRowF;
                ldsm_x4(afh[mt][0], afh[mt][1], afh[mt][2], afh[mt][3],
                        smem_u32(aH + row * A_STR + ks * 16 + aColF));
                ldsm_x4(afl[mt][0], afl[mt][1], afl[mt][2], afl[mt][3],
                        smem_u32(aL + row * A_STR + ks * 16 + aColF));
            }
            #pragma unroll
            for (int p = 0; p < 4; p++) {
                ldsm_x4t(bf[2*p][0], bf[2*p][1], bf[2*p+1][0], bf[2*p+1][1],
                         smem_u32(bH + (ks * 16 + bRowT) * B_STR + wn + p * 16 + bNT));
            }
            #pragma unroll
            for (int mt = 0; mt < 2; mt++)
                #pragma unroll
                for (int nt = 0; nt < 8; nt++) {
                    mma16816(acc[mt][nt], afh[mt][0], afh[mt][1], afh[mt][2], afh[mt][3],
                             bf[nt][0], bf[nt][1]);
                    mma16816(acc[mt][nt], afl[mt][0], afl[mt][1], afl[mt][2], afl[mt][3],
                             bf[nt][0], bf[nt][1]);
                }
        }

        if (kt + 1 < nk) {
            cp_wait0();
            __syncthreads();
            buf ^= 1;
        }
    }

    #pragma unroll
    for (int mt = 0; mt < 2; mt++) {
        const int r0 = blockIdx.y * 128 + wm + mt * 16 + (lane >> 2);
        #pragma unroll
        for (int nt = 0; nt < 8; nt++) {
            const int c0 = bCol + wn + nt * 8 + (lane & 3) * 2;
            const float b0 = bias[c0], b1 = bias[c0 + 1];
            const float v00 = acc[mt][nt][0] + b0, v01 = acc[mt][nt][1] + b1;
            const float v10 = acc[mt][nt][2] + b0, v11 = acc[mt][nt][3] + b1;
            if (OUT_HALF) {
                const __half h00 = __float2half_rn(v00), h01 = __float2half_rn(v01);
                const __half h10 = __float2half_rn(v10), h11 = __float2half_rn(v11);
                *(__half2*)(Chi + (size_t)r0 * N + c0)       = __halves2half2(h00, h01);
                *(__half2*)(Chi + (size_t)(r0 + 8) * N + c0) = __halves2half2(h10, h11);
                if (c0 < CDIM) {   // lo only consumed for Q columns
                    *(__half2*)(Clo + (size_t)r0 * N + c0)       = __halves2half2(
                        __float2half_rn(v00 - __half2float(h00)),
                        __float2half_rn(v01 - __half2float(h01)));
                    *(__half2*)(Clo + (size_t)(r0 + 8) * N + c0) = __halves2half2(
                        __float2half_rn(v10 - __half2float(h10)),
                        __float2half_rn(v11 - __half2float(h11)));
                }
            } else {
                *(float2*)(C + (size_t)r0 * N + c0)       = make_float2(v00, v01);
                *(float2*)(C + (size_t)(r0 + 8) * N + c0) = make_float2(v10, v11);
            }
        }
    }
}

// ---------------------------------------------------------------------------
// Tensor-core flash attention, split-2 Q, P hi-only:
//   S = (Qhi+Qlo)@Khi^T, P = exp2(S*qs - rl*dist), O = Phi@Vhi.
// (Plo correction dropped: adds ~1.2e-4 RMS, total ~5.0e-4 < 1e-3.)
// 3 CTAs/SM. Window 14/r.
// ---------------------------------------------------------------------------
#define KV_STR 72
#define AT_BUF (64 * KV_STR)
#define AT_STAGE (2 * AT_BUF)                 // K hi, V hi
#define AT_SMEM ((2 * AT_BUF + 2 * AT_STAGE) * 2)   // bytes (~55 KB)

__global__ void __launch_bounds__(128, 3) attn_mma(
    const __half* __restrict__ qkhi, const __half* __restrict__ qklo,
    const float* __restrict__ decay,
    __half* __restrict__ yhi, __half* __restrict__ ylo)
{
    extern __shared__ __align__(16) __half asm_[];
    __half* QsH = asm_;
    __half* QsL = asm_ + AT_BUF;

    const int q0   = blockIdx.x * 64;
    const int h    = blockIdx.y;
    const int bb   = blockIdx.z;
    const int t    = threadIdx.x;
    const int warp = t >> 5;
    const int lane = t & 31;

    const size_t rowBase = (size_t)bb * SEQ;
    const float r  = decay[h];
    const float rl = r * LOG2E;
    const float qs = 0.125f * LOG2E;

    {
        #pragma unroll
        for (int it = 0; it < 4; it++) {
            const int u = it * 128 + t;
            const int row = u >> 3;
            const int c = (u & 7) * 8;
            const size_t gsrc = (rowBase + q0 + row) * C3 + h * HD + c;
            cp16(smem_u32(QsH + row * KV_STR + c), qkhi + gsrc);
            cp16(smem_u32(QsL + row * KV_STR + c), qklo + gsrc);
        }
        cp_commit();
    }

    auto load_kv = [&](int s, int k0) {
        __half* st = asm_ + 2 * AT_BUF + s * AT_STAGE;
        __half* kH = st;
        __half* vH = st + AT_BUF;
        #pragma unroll
        for (int it = 0; it < 4; it++) {
            const int u = it * 128 + t;
            const int row = u >> 3;
            const int c = (u & 7) * 8;
            const size_t gk = (rowBase + k0 + row) * C3 + CDIM + h * HD + c;
            cp16(smem_u32(kH + row * KV_STR + c), qkhi + gk);
            cp16(smem_u32(vH + row * KV_STR + c), qkhi + gk + CDIM);
        }
        cp_commit();
    };

    const int W = (r > 1e-6f) ? (int)(14.0f / r) : (1 << 30);
    int km = q0 - W;
    if (km < 0) km = 0;
    const int kstart = (km / 64) * 64;

    load_kv(0, kstart);
    cp_wait0();
    __syncthreads();

    const int lr   = lane & 7;
    const int aRow = lr + ((lane >> 3) & 1) * 8;
    const int aCol = (lane >> 4) * 8;
    const int kN   = ((lane >> 4) & 1) * 8;
    const int kK   = ((lane >> 3) & 1) * 8;
    const int vRow = lane & 15;
    const int vN   = (lane >> 4) * 8;

    uint32_t qh[4][4], ql[4][4];
    #pragma unroll
    for (int ks = 0; ks < 4; ks++) {
        ldsm_x4(qh[ks][0], qh[ks][1], qh[ks][2], qh[ks][3],
                smem_u32(QsH + (warp * 16 + aRow) * KV_STR + ks * 16 + aCol));
        ldsm_x4(ql[ks][0], ql[ks][1], ql[ks][2], ql[ks][3],
                smem_u32(QsL + (warp * 16 + aRow) * KV_STR + ks * 16 + aCol));
    }

    float O[8][4];
    #pragma unroll
    for (int nt = 0; nt < 8; nt++)
        #pragma unroll
        for (int i = 0; i < 4; i++) O[nt][i] = 0.0f;
    float lsum0 = 0.0f, lsum1 = 0.0f;

    int buf = 0;
    for (int k0 = kstart; k0 <= q0; k0 += 64) {
        if (k0 != kstart) {
            cp_wait0();
            __syncthreads();
        }
        if (k0 + 64 <= q0) load_kv(buf ^ 1, k0 + 64);

        __half* st = asm_ + 2 * AT_BUF + buf * AT_STAGE;
        const __half* KsH = st;
        const __half* VsH = st + AT_BUF;

        float S[8][4];
        #pragma unroll
        for (int nt = 0; nt < 8; nt++)
            #pragma unroll
            for (int i = 0; i < 4; i++) S[nt][i] = 0.0f;

        #pragma unroll
        for (int ks = 0; ks < 4; ks++) {
            #pragma unroll
            for (int np = 0; np < 4; np++) {
                uint32_t b0, b1, b2, b3;
                ldsm_x4(b0, b1, b2, b3,
                        smem_u32(KsH + (np * 16 + kN + lr) * KV_STR + ks * 16 + kK));
                mma16816(S[2*np],   qh[ks][0], qh[ks][1], qh[ks][2], qh[ks][3], b0, b1);
                mma16816(S[2*np+1], qh[ks][0], qh[ks][1], qh[ks][2], qh[ks][3], b2, b3);
                mma16816(S[2*np],   ql[ks][0], ql[ks][1], ql[ks][2], ql[ks][3], b0, b1);
                mma16816(S[2*np+1], ql[ks][0], ql[ks][1], ql[ks][2], ql[ks][3], b2, b3);
            }
        }

        // P = exp2(S*qs - rl*dist), causal; hi fp16 only
        uint32_t PH0[8], PH1[8];
        const float i0f = (float)(q0 + warp * 16 + (lane >> 2) - k0);
        const float i1f = i0f + 8.0f;
        const float jcb = (float)((lane & 3) * 2);
        #pragma unroll
        for (int nt = 0; nt < 8; nt++) {
            const float jc  = (float)(nt * 8) + jcb;
            const float d00 = i0f - jc, d01 = d00 - 1.0f;
            const float d10 = i1f - jc, d11 = d10 - 1.0f;
            const float p00 = (d00 >= 0.0f) ? ex2(fmaf(S[nt][0], qs, -rl * d00)) : 0.0f;
            const float p01 = (d01 >= 0.0f) ? ex2(fmaf(S[nt][1], qs, -rl * d01)) : 0.0f;
            const float p10 = (d10 >= 0.0f) ? ex2(fmaf(S[nt][2], qs, -rl * d10)) : 0.0f;
            const float p11 = (d11 >= 0.0f) ? ex2(fmaf(S[nt][3], qs, -rl * d11)) : 0.0f;
            lsum0 += p00 + p01;
            lsum1 += p10 + p11;
            __half2 hh0 = __halves2half2(__float2half_rn(p00), __float2half_rn(p01));
            __half2 hh1 = __halves2half2(__float2half_rn(p10), __float2half_rn(p11));
            PH0[nt] = *reinterpret_cast<uint32_t*>(&hh0);
            PH1[nt] = *reinterpret_cast<uint32_t*>(&hh1);
        }

        // O += Phi @ Vhi
        #pragma unroll
        for (int ks = 0; ks < 4; ks++) {
            const uint32_t a0 = PH0[2*ks], a1 = PH1[2*ks], a2 = PH0[2*ks+1], a3 = PH1[2*ks+1];
            #pragma unroll
            for (int np = 0; np < 4; np++) {
                uint32_t v0, v1, v2, v3;
                ldsm_x4t(v0, v1, v2, v3,
                         smem_u32(VsH + (ks * 16 + vRow) * KV_STR + np * 16 + vN));
                mma16816(O[2*np],   a0, a1, a2, a3, v0, v1);
                mma16816(O[2*np+1], a0, a1, a2, a3, v2, v3);
            }
        }
        buf ^= 1;
    }

    lsum0 += __shfl_xor_sync(0xffffffffu, lsum0, 1);
    lsum0 += __shfl_xor_sync(0xffffffffu, lsum0, 2);
    lsum1 += __shfl_xor_sync(0xffffffffu, lsum1, 1);
    lsum1 += __shfl_xor_sync(0xffffffffu, lsum1, 2);
    const float inv0 = 1.0f / lsum0;
    const float inv1 = 1.0f / lsum1;

    const int irow = q0 + warp * 16 + (lane >> 2);
    const size_t rb0 = (rowBase + irow) * CDIM + h * HD;
    const size_t rb1 = rb0 + (size_t)8 * CDIM;
    #pragma unroll
    for (int nt = 0; nt < 8; nt++) {
        const int col = nt * 8 + (lane & 3) * 2;
        const float y0 = O[nt][0] * inv0, y1 = O[nt][1] * inv0;
        const float y2 = O[nt][2] * inv1, y3 = O[nt][3] * inv1;
        const __half a0 = __float2half_rn(y0), a1 = __float2half_rn(y1);
        const __half a2 = __float2half_rn(y2), a3 = __float2half_rn(y3);
        *(__half2*)(yhi + rb0 + col) = __halves2half2(a0, a1);
        *(__half2*)(yhi + rb1 + col) = __halves2half2(a2, a3);
        *(__half2*)(ylo + rb0 + col) = __halves2half2(
            __float2half_rn(y0 - __half2float(a0)), __float2half_rn(y1 - __half2float(a1)));
        *(__half2*)(ylo + rb1 + col) = __halves2half2(
            __float2half_rn(y2 - __half2float(a2)), __float2half_rn(y3 - __half2float(a3)));
    }
}

// ---------------------------------------------------------------------------
extern "C" void kernel_launch(void* const* d_in, const int* in_sizes, int n_in,
                              void* d_out, int out_size)
{
    const float* x      = (const float*)d_in[0];
    const float* W_attn = (const float*)d_in[1];
    const float* b_attn = (const float*)d_in[2];
    const float* W_proj = (const float*)d_in[3];
    const float* b_proj = (const float*)d_in[4];
    const float* decay  = (const float*)d_in[5];
    float* out = (float*)d_out;

    __half *qkhi, *qklo, *xhi, *xlo, *wahi, *wphi, *yhi, *ylo;
    cudaGetSymbolAddress((void**)&qkhi, g_qkhi);
    cudaGetSymbolAddress((void**)&qklo, g_qklo);
    cudaGetSymbolAddress((void**)&xhi,  g_xhi);
    cudaGetSymbolAddress((void**)&xlo,  g_xlo);
    cudaGetSymbolAddress((void**)&wahi, g_wahi);
    cudaGetSymbolAddress((void**)&wphi, g_wphi);
    cudaGetSymbolAddress((void**)&yhi,  g_yhi);
    cudaGetSymbolAddress((void**)&ylo,  g_ylo);

    static bool attr_set = false;
    if (!attr_set) {
        cudaFuncSetAttribute((const void*)hgemm_split<true>,
                             cudaFuncAttributeMaxDynamicSharedMemorySize, HG_SMEM);
        cudaFuncSetAttribute((const void*)hgemm_split<false>,
                             cudaFuncAttributeMaxDynamicSharedMemorySize, HG_SMEM);
        cudaFuncSetAttribute((const void*)attn_mma,
                             cudaFuncAttributeMaxDynamicSharedMemorySize, AT_SMEM);
        attr_set = true;
    }

    // 0) x: hi/lo split; weights: hi-only convert
    {
        int n4 = MROWS * CDIM / 4;
        split_fp32<<<(n4 + 255) / 256, 256>>>((const float4*)x, (__half2*)xhi, (__half2*)xlo, n4);
        n4 = CDIM * C3 / 4;
        cvt_fp16<<<(n4 + 255) / 256, 256>>>((const float4*)W_attn, (__half2*)wahi, n4);
        n4 = CDIM * CDIM / 4;
        cvt_fp16<<<(n4 + 255) / 256, 256>>>((const float4*)W_proj, (__half2*)wphi, n4);
    }
    // 1) qkv = x @ W_attn + b_attn -> fp16 hi (+lo for Q cols)
    {
        dim3 grid(C3 / 128, MROWS / 128);
        hgemm_split<true><<<grid, 256, HG_SMEM>>>(
            xhi, xlo, wahi, b_attn, nullptr, qkhi, qklo, C3, CDIM);
    }
    // 2) fused decay attention -> yhi/ylo
    {
        dim3 grid(SEQ / 64, NHEAD, BATCH);
        attn_mma<<<grid, 128, AT_SMEM>>>(qkhi, qklo, decay, yhi, ylo);
    }
    // 3) out = y @ W_proj + b_proj -> fp32
    {
        dim3 grid(CDIM / 128, MROWS / 128);
        hgemm_split<false><<<grid, 256, HG_SMEM>>>(
            yhi, ylo, wphi, b_proj, out, nullptr, nullptr, CDIM, CDIM);
    }
}

// round 16
// speedup vs baseline: 1.2555x; 1.1147x over previous
#include <cuda_runtime.h>
#include <cuda_fp16.h>
#include <cstdint>

// Problem constants (fixed by setup_inputs)
#define BATCH 4
#define SEQ   2048
#define CDIM  768
#define NHEAD 12
#define HD    64
#define MROWS (BATCH*SEQ)      // 8192
#define C3    (3*CDIM)         // 2304
#define LOG2E 1.4426950408889634f

// Scratch (device globals; no runtime allocation)
__device__ __half g_qkhi[(size_t)MROWS * C3];
__device__ __half g_xhi[(size_t)MROWS * CDIM];
__device__ __half g_xlo[(size_t)MROWS * CDIM];
__device__ __half g_wahi[(size_t)CDIM * C3];     // weights: hi only
__device__ __half g_wphi[(size_t)CDIM * CDIM];
__device__ __half g_yhi[(size_t)MROWS * CDIM];

__device__ __forceinline__ float ex2(float x) {
    float y;
    asm("ex2.approx.f32 %0, %1;" : "=f"(y) : "f"(x));
    return y;
}
__device__ __forceinline__ uint32_t smem_u32(const void* p) {
    return (uint32_t)__cvta_generic_to_shared(p);
}
__device__ __forceinline__ void cp16(uint32_t dst, const void* src) {
    asm volatile("cp.async.ca.shared.global [%0], [%1], 16;\n" :: "r"(dst), "l"(src));
}
__device__ __forceinline__ void cp_commit() {
    asm volatile("cp.async.commit_group;\n" ::: "memory");
}
__device__ __forceinline__ void cp_wait0() {
    asm volatile("cp.async.wait_group 0;\n" ::: "memory");
}
__device__ __forceinline__ void ldsm_x4(uint32_t& r0, uint32_t& r1, uint32_t& r2, uint32_t& r3,
                                        uint32_t addr) {
    asm volatile("ldmatrix.sync.aligned.m8n8.x4.shared.b16 {%0,%1,%2,%3}, [%4];"
                 : "=r"(r0), "=r"(r1), "=r"(r2), "=r"(r3) : "r"(addr));
}
__device__ __forceinline__ void ldsm_x4t(uint32_t& r0, uint32_t& r1, uint32_t& r2, uint32_t& r3,
                                         uint32_t addr) {
    asm volatile("ldmatrix.sync.aligned.m8n8.x4.trans.shared.b16 {%0,%1,%2,%3}, [%4];"
                 : "=r"(r0), "=r"(r1), "=r"(r2), "=r"(r3) : "r"(addr));
}
__device__ __forceinline__ void mma16816(float* c,
                                         uint32_t a0, uint32_t a1, uint32_t a2, uint32_t a3,
                                         uint32_t b0, uint32_t b1) {
    asm volatile("mma.sync.aligned.m16n8k16.row.col.f32.f16.f16.f32 "
                 "{%0,%1,%2,%3}, {%4,%5,%6,%7}, {%8,%9}, {%0,%1,%2,%3};"
                 : "+f"(c[0]), "+f"(c[1]), "+f"(c[2]), "+f"(c[3])
                 : "r"(a0), "r"(a1), "r"(a2), "r"(a3), "r"(b0), "r"(b1));
}

// ---------------------------------------------------------------------------
// fp32 -> (fp16 hi, fp16 lo) split, vectorized by 4. (x only)
// ---------------------------------------------------------------------------
__global__ void __launch_bounds__(256) split_fp32(
    const float4* __restrict__ src, __half2* __restrict__ hi,
    __half2* __restrict__ lo, int n4)
{
    const int i = blockIdx.x * blockDim.x + threadIdx.x;
    if (i >= n4) return;
    float4 v = src[i];
    __half h0 = __float2half_rn(v.x), h1 = __float2half_rn(v.y);
    __half h2 = __float2half_rn(v.z), h3 = __float2half_rn(v.w);
    hi[2*i]   = __halves2half2(h0, h1);
    hi[2*i+1] = __halves2half2(h2, h3);
    lo[2*i]   = __halves2half2(__float2half_rn(v.x - __half2float(h0)),
                               __float2half_rn(v.y - __half2float(h1)));
    lo[2*i+1] = __halves2half2(__float2half_rn(v.z - __half2float(h2)),
                               __float2half_rn(v.w - __half2float(h3)));
}

// fp32 -> fp16 convert only (weights)
__global__ void __launch_bounds__(256) cvt_fp16(
    const float4* __restrict__ src, __half2* __restrict__ hi, int n4)
{
    const int i = blockIdx.x * blockDim.x + threadIdx.x;
    if (i >= n4) return;
    float4 v = src[i];
    hi[2*i]   = __halves2half2(__float2half_rn(v.x), __float2half_rn(v.y));
    hi[2*i+1] = __halves2half2(__float2half_rn(v.z), __float2half_rn(v.w));
}

// ---------------------------------------------------------------------------
// fp16 tensor-core GEMM + bias, cp.async double-buffered, BK=32.
//   SPLIT_A=1: C = (Ahi+Alo)@Bhi + bias  (GEMM1)
//   SPLIT_A=0: C = Ahi@Bhi + bias        (GEMM2)
// OUT_HALF=1: write fp16 hi. Else fp32.
// Warp grid 4x2 (warp tile 32x64): measured-best.
// ---------------------------------------------------------------------------
#define BK    32
#define A_STR 40
#define B_STR 136
#define HG_ABUF (128 * A_STR)
#define HG_BBUF (BK * B_STR)

template<bool OUT_HALF, bool SPLIT_A>
__global__ void __launch_bounds__(256, 2) hgemm_split(
    const __half* __restrict__ Ahi, const __half* __restrict__ Alo,
    const __half* __restrict__ Bhi,
    const float* __restrict__ bias, float* __restrict__ C,
    __half* __restrict__ Chi,
    int N, int K)
{
    constexpr int NA    = SPLIT_A ? 2 : 1;
    constexpr int STAGE = NA * HG_ABUF + HG_BBUF;

    extern __shared__ __align__(16) __half hsm[];

    const int t    = threadIdx.x;
    const int warp = t >> 5;
    const int lane = t & 31;
    const int wm   = (warp >> 1) * 32;    // 4 m-stripes
    const int wn   = (warp & 1) * 64;     // 2 n-stripes

    const size_t aG   = (size_t)blockIdx.y * 128 * K;
    const int    bCol = blockIdx.x * 128;

    const int g     = lane >> 3;
    const int lr    = lane & 7;
    const int aRowF = (g & 1) * 8 + lr;
    const int aColF = (g >> 1) * 8;
    const int bRowT = lane & 15;
    const int bNT   = (lane >> 4) * 8;

    float acc[2][8][4];
    #pragma unroll
    for (int mt = 0; mt < 2; mt++)
        #pragma unroll
        for (int nt = 0; nt < 8; nt++)
            #pragma unroll
            for (int i = 0; i < 4; i++) acc[mt][nt][i] = 0.0f;

    auto load_tile = [&](int s, int ko) {
        __half* base = hsm + s * STAGE;
        __half* aH = base;
        __half* aL = base + HG_ABUF;          // only used if SPLIT_A
        __half* bH = base + NA * HG_ABUF;
        #pragma unroll
        for (int it = 0; it < 2; it++) {
            const int u   = it * 256 + t;
            const int row = u >> 2;
            const int c   = (u & 3) * 8;
            const size_t gsrc = aG + (size_t)row * K + ko + c;
            cp16(smem_u32(aH + row * A_STR + c), Ahi + gsrc);
            if (SPLIT_A)
                cp16(smem_u32(aL + row * A_STR + c), Alo + gsrc);
        }
        #pragma unroll
        for (int it = 0; it < 2; it++) {
            const int u   = it * 256 + t;
            const int row = u >> 4;
            const int c   = (u & 15) * 8;
            cp16(smem_u32(bH + row * B_STR + c), Bhi + (size_t)(ko + row) * N + bCol + c);
        }
        cp_commit();
    };

    load_tile(0, 0);
    cp_wait0();
    __syncthreads();

    const int nk = K / BK;
    int buf = 0;
    for (int kt = 0; kt < nk; kt++) {
        if (kt + 1 < nk) load_tile(buf ^ 1, (kt + 1) * BK);

        const __half* base = hsm + buf * STAGE;
        const __half* aH = base;
        const __half* aL = base + HG_ABUF;
        const __half* bH = base + NA * HG_ABUF;

        #pragma unroll
        for (int ks = 0; ks < 2; ks++) {
            uint32_t afh[2][4], afl[2][4], bf[8][2];
            #pragma unroll
            for (int mt = 0; mt < 2; mt++) {
                const int row = wm + mt * 16 + aRowF;
                ldsm_x4(afh[mt][0], afh[mt][1], afh[mt][2], afh[mt][3],
                        smem_u32(aH + row * A_STR + ks * 16 + aColF));
                if (SPLIT_A)
                    ldsm_x4(afl[mt][0], afl[mt][1], afl[mt][2], afl[mt][3],
                            smem_u32(aL + row * A_STR + ks * 16 + aColF));
            }
            #pragma unroll
            for (int p = 0; p < 4; p++) {
                ldsm_x4t(bf[2*p][0], bf[2*p][1], bf[2*p+1][0], bf[2*p+1][1],
                         smem_u32(bH + (ks * 16 + bRowT) * B_STR + wn + p * 16 + bNT));
            }
            #pragma unroll
            for (int mt = 0; mt < 2; mt++)
                #pragma unroll
                for (int nt = 0; nt < 8; nt++) {
                    mma16816(acc[mt][nt], afh[mt][0], afh[mt][1], afh[mt][2], afh[mt][3],
                             bf[nt][0], bf[nt][1]);
                    if (SPLIT_A)
                        mma16816(acc[mt][nt], afl[mt][0], afl[mt][1], afl[mt][2], afl[mt][3],
                                 bf[nt][0], bf[nt][1]);
                }
        }

        if (kt + 1 < nk) {
            cp_wait0();
            __syncthreads();
            buf ^= 1;
        }
    }

    #pragma unroll
    for (int mt = 0; mt < 2; mt++) {
        const int r0 = blockIdx.y * 128 + wm + mt * 16 + (lane >> 2);
        #pragma unroll
        for (int nt = 0; nt < 8; nt++) {
            const int c0 = bCol + wn + nt * 8 + (lane & 3) * 2;
            const float b0 = bias[c0], b1 = bias[c0 + 1];
            const float v00 = acc[mt][nt][0] + b0, v01 = acc[mt][nt][1] + b1;
            const float v10 = acc[mt][nt][2] + b0, v11 = acc[mt][nt][3] + b1;
            if (OUT_HALF) {
                *(__half2*)(Chi + (size_t)r0 * N + c0) =
                    __halves2half2(__float2half_rn(v00), __float2half_rn(v01));
                *(__half2*)(Chi + (size_t)(r0 + 8) * N + c0) =
                    __halves2half2(__float2half_rn(v10), __float2half_rn(v11));
            } else {
                *(float2*)(C + (size_t)r0 * N + c0)       = make_float2(v00, v01);
                *(float2*)(C + (size_t)(r0 + 8) * N + c0) = make_float2(v10, v11);
            }
        }
    }
}

#define HG_SMEM_S2 ((2 * HG_ABUF + HG_BBUF) * 2 * 2)   // split-A stage x2
#define HG_SMEM_S1 ((HG_ABUF + HG_BBUF) * 2 * 2)       // plain stage x2

// ---------------------------------------------------------------------------
// Tensor-core flash attention, all-hi fp16:
//   S = Qhi@Khi^T, P = exp2(S*qs - rl*dist), O = Phi@Vhi, y = O/l (hi fp16).
// 3 CTAs/SM. Window 14/r.
// ---------------------------------------------------------------------------
#define KV_STR 72
#define AT_BUF (64 * KV_STR)
#define AT_STAGE (2 * AT_BUF)                 // K hi, V hi
#define AT_SMEM ((AT_BUF + 2 * AT_STAGE) * 2)   // bytes (~45 KB)

__global__ void __launch_bounds__(128, 3) attn_mma(
    const __half* __restrict__ qkhi, const float* __restrict__ decay,
    __half* __restrict__ yhi)
{
    extern __shared__ __align__(16) __half asm_[];
    __half* QsH = asm_;

    const int q0   = blockIdx.x * 64;
    const int h    = blockIdx.y;
    const int bb   = blockIdx.z;
    const int t    = threadIdx.x;
    const int warp = t >> 5;
    const int lane = t & 31;

    const size_t rowBase = (size_t)bb * SEQ;
    const float r  = decay[h];
    const float rl = r * LOG2E;
    const float qs = 0.125f * LOG2E;

    {
        #pragma unroll
        for (int it = 0; it < 4; it++) {
            const int u = it * 128 + t;
            const int row = u >> 3;
            const int c = (u & 7) * 8;
            const size_t gsrc = (rowBase + q0 + row) * C3 + h * HD + c;
            cp16(smem_u32(QsH + row * KV_STR + c), qkhi + gsrc);
        }
        cp_commit();
    }

    auto load_kv = [&](int s, int k0) {
        __half* st = asm_ + AT_BUF + s * AT_STAGE;
        __half* kH = st;
        __half* vH = st + AT_BUF;
        #pragma unroll
        for (int it = 0; it < 4; it++) {
            const int u = it * 128 + t;
            const int row = u >> 3;
            const int c = (u & 7) * 8;
            const size_t gk = (rowBase + k0 + row) * C3 + CDIM + h * HD + c;
            cp16(smem_u32(kH + row * KV_STR + c), qkhi + gk);
            cp16(smem_u32(vH + row * KV_STR + c), qkhi + gk + CDIM);
        }
        cp_commit();
    };

    const int W = (r > 1e-6f) ? (int)(14.0f / r) : (1 << 30);
    int km = q0 - W;
    if (km < 0) km = 0;
    const int kstart = (km / 64) * 64;

    load_kv(0, kstart);
    cp_wait0();
    __syncthreads();

    const int lr   = lane & 7;
    const int aRow = lr + ((lane >> 3) & 1) * 8;
    const int aCol = (lane >> 4) * 8;
    const int kN   = ((lane >> 4) & 1) * 8;
    const int kK   = ((lane >> 3) & 1) * 8;
    const int vRow = lane & 15;
    const int vN   = (lane >> 4) * 8;

    uint32_t qh[4][4];
    #pragma unroll
    for (int ks = 0; ks < 4; ks++) {
        ldsm_x4(qh[ks][0], qh[ks][1], qh[ks][2], qh[ks][3],
                smem_u32(QsH + (warp * 16 + aRow) * KV_STR + ks * 16 + aCol));
    }

    float O[8][4];
    #pragma unroll
    for (int nt = 0; nt < 8; nt++)
        #pragma unroll
        for (int i = 0; i < 4; i++) O[nt][i] = 0.0f;
    float lsum0 = 0.0f, lsum1 = 0.0f;

    int buf = 0;
    for (int k0 = kstart; k0 <= q0; k0 += 64) {
        if (k0 != kstart) {
            cp_wait0();
            __syncthreads();
        }
        if (k0 + 64 <= q0) load_kv(buf ^ 1, k0 + 64);

        __half* st = asm_ + AT_BUF + buf * AT_STAGE;
        const __half* KsH = st;
        const __half* VsH = st + AT_BUF;

        float S[8][4];
        #pragma unroll
        for (int nt = 0; nt < 8; nt++)
            #pragma unroll
            for (int i = 0; i < 4; i++) S[nt][i] = 0.0f;

        #pragma unroll
        for (int ks = 0; ks < 4; ks++) {
            #pragma unroll
            for (int np = 0; np < 4; np++) {
                uint32_t b0, b1, b2, b3;
                ldsm_x4(b0, b1, b2, b3,
                        smem_u32(KsH + (np * 16 + kN + lr) * KV_STR + ks * 16 + kK));
                mma16816(S[2*np],   qh[ks][0], qh[ks][1], qh[ks][2], qh[ks][3], b0, b1);
                mma16816(S[2*np+1], qh[ks][0], qh[ks][1], qh[ks][2], qh[ks][3], b2, b3);
            }
        }

        // P = exp2(S*qs - rl*dist), causal; hi fp16
        uint32_t PH0[8], PH1[8];
        const float i0f = (float)(q0 + warp * 16 + (lane >> 2) - k0);
        const float i1f = i0f + 8.0f;
        const float jcb = (float)((lane & 3) * 2);
        #pragma unroll
        for (int nt = 0; nt < 8; nt++) {
            const float jc  = (float)(nt * 8) + jcb;
            const float d00 = i0f - jc, d01 = d00 - 1.0f;
            const float d10 = i1f - jc, d11 = d10 - 1.0f;
            const float p00 = (d00 >= 0.0f) ? ex2(fmaf(S[nt][0], qs, -rl * d00)) : 0.0f;
            const float p01 = (d01 >= 0.0f) ? ex2(fmaf(S[nt][1], qs, -rl * d01)) : 0.0f;
            const float p10 = (d10 >= 0.0f) ? ex2(fmaf(S[nt][2], qs, -rl * d10)) : 0.0f;
            const float p11 = (d11 >= 0.0f) ? ex2(fmaf(S[nt][3], qs, -rl * d11)) : 0.0f;
            lsum0 += p00 + p01;
            lsum1 += p10 + p11;
            __half2 hh0 = __halves2half2(__float2half_rn(p00), __float2half_rn(p01));
            __half2 hh1 = __halves2half2(__float2half_rn(p10), __float2half_rn(p11));
            PH0[nt] = *reinterpret_cast<uint32_t*>(&hh0);
            PH1[nt] = *reinterpret_cast<uint32_t*>(&hh1);
        }

        // O += Phi @ Vhi
        #pragma unroll
        for (int ks = 0; ks < 4; ks++) {
            const uint32_t a0 = PH0[2*ks], a1 = PH1[2*ks], a2 = PH0[2*ks+1], a3 = PH1[2*ks+1];
            #pragma unroll
            for (int np = 0; np < 4; np++) {
                uint32_t v0, v1, v2, v3;
                ldsm_x4t(v0, v1, v2, v3,
                         smem_u32(VsH + (ks * 16 + vRow) * KV_STR + np * 16 + vN));
                mma16816(O[2*np],   a0, a1, a2, a3, v0, v1);
                mma16816(O[2*np+1], a0, a1, a2, a3, v2, v3);
            }
        }
        buf ^= 1;
    }

    lsum0 += __shfl_xor_sync(0xffffffffu, lsum0, 1);
    lsum0 += __shfl_xor_sync(0xffffffffu, lsum0, 2);
    lsum1 += __shfl_xor_sync(0xffffffffu, lsum1, 1);
    lsum1 += __shfl_xor_sync(0xffffffffu, lsum1, 2);
    const float inv0 = 1.0f / lsum0;
    const float inv1 = 1.0f / lsum1;

    const int irow = q0 + warp * 16 + (lane >> 2);
    const size_t rb0 = (rowBase + irow) * CDIM + h * HD;
    const size_t rb1 = rb0 + (size_t)8 * CDIM;
    #pragma unroll
    for (int nt = 0; nt < 8; nt++) {
        const int col = nt * 8 + (lane & 3) * 2;
        *(__half2*)(yhi + rb0 + col) = __halves2half2(
            __float2half_rn(O[nt][0] * inv0), __float2half_rn(O[nt][1] * inv0));
        *(__half2*)(yhi + rb1 + col) = __halves2half2(
            __float2half_rn(O[nt][2] * inv1), __float2half_rn(O[nt][3] * inv1));
    }
}

// ---------------------------------------------------------------------------
extern "C" void kernel_launch(void* const* d_in, const int* in_sizes, int n_in,
                              void* d_out, int out_size)
{
    const float* x      = (const float*)d_in[0];
    const float* W_attn = (const float*)d_in[1];
    const float* b_attn = (const float*)d_in[2];
    const float* W_proj = (const float*)d_in[3];
    const float* b_proj = (const float*)d_in[4];
    const float* decay  = (const float*)d_in[5];
    float* out = (float*)d_out;

    __half *qkhi, *xhi, *xlo, *wahi, *wphi, *yhi;
    cudaGetSymbolAddress((void**)&qkhi, g_qkhi);
    cudaGetSymbolAddress((void**)&xhi,  g_xhi);
    cudaGetSymbolAddress((void**)&xlo,  g_xlo);
    cudaGetSymbolAddress((void**)&wahi, g_wahi);
    cudaGetSymbolAddress((void**)&wphi, g_wphi);
    cudaGetSymbolAddress((void**)&yhi,  g_yhi);

    static bool attr_set = false;
    if (!attr_set) {
        cudaFuncSetAttribute((const void*)hgemm_split<true, true>,
                             cudaFuncAttributeMaxDynamicSharedMemorySize, HG_SMEM_S2);
        cudaFuncSetAttribute((const void*)hgemm_split<false, false>,
                             cudaFuncAttributeMaxDynamicSharedMemorySize, HG_SMEM_S1);
        cudaFuncSetAttribute((const void*)attn_mma,
                             cudaFuncAttributeMaxDynamicSharedMemorySize, AT_SMEM);
        attr_set = true;
    }

    // 0) x: hi/lo split; weights: hi-only convert
    {
        int n4 = MROWS * CDIM / 4;
        split_fp32<<<(n4 + 255) / 256, 256>>>((const float4*)x, (__half2*)xhi, (__half2*)xlo, n4);
        n4 = CDIM * C3 / 4;
        cvt_fp16<<<(n4 + 255) / 256, 256>>>((const float4*)W_attn, (__half2*)wahi, n4);
        n4 = CDIM * CDIM / 4;
        cvt_fp16<<<(n4 + 255) / 256, 256>>>((const float4*)W_proj, (__half2*)wphi, n4);
    }
    // 1) qkv = x @ W_attn + b_attn -> fp16 hi  (split-2 A)
    {
        dim3 grid(C3 / 128, MROWS / 128);
        hgemm_split<true, true><<<grid, 256, HG_SMEM_S2>>>(
            xhi, xlo, wahi, b_attn, nullptr, qkhi, C3, CDIM);
    }
    // 2) fused decay attention -> yhi
    {
        dim3 grid(SEQ / 64, NHEAD, BATCH);
        attn_mma<<<grid, 128, AT_SMEM>>>(qkhi, decay, yhi);
    }
    // 3) out = y @ W_proj + b_proj -> fp32  (plain hi GEMM)
    {
        dim3 grid(CDIM / 128, MROWS / 128);
        hgemm_split<false, false><<<grid, 256, HG_SMEM_S1>>>(
            yhi, nullptr, wphi, b_proj, out, nullptr, CDIM, CDIM);
    }
}

// round 17
// speedup vs baseline: 1.6483x; 1.3129x over previous
#include <cuda_runtime.h>
#include <cuda_fp16.h>
#include <cstdint>

// Problem constants (fixed by setup_inputs)
#define BATCH 4
#define SEQ   2048
#define CDIM  768
#define NHEAD 12
#define HD    64
#define MROWS (BATCH*SEQ)      // 8192
#define C3    (3*CDIM)         // 2304
#define LOG2E 1.4426950408889634f

// Scratch (device globals; no runtime allocation)
__device__ __half g_qkhi[(size_t)MROWS * C3];
__device__ __half g_xhi[(size_t)MROWS * CDIM];
__device__ __half g_wahi[(size_t)CDIM * C3];
__device__ __half g_wphi[(size_t)CDIM * CDIM];
__device__ __half g_yhi[(size_t)MROWS * CDIM];

__device__ __forceinline__ float ex2(float x) {
    float y;
    asm("ex2.approx.f32 %0, %1;" : "=f"(y) : "f"(x));
    return y;
}
__device__ __forceinline__ uint32_t smem_u32(const void* p) {
    return (uint32_t)__cvta_generic_to_shared(p);
}
__device__ __forceinline__ void cp16(uint32_t dst, const void* src) {
    asm volatile("cp.async.ca.shared.global [%0], [%1], 16;\n" :: "r"(dst), "l"(src));
}
__device__ __forceinline__ void cp_commit() {
    asm volatile("cp.async.commit_group;\n" ::: "memory");
}
__device__ __forceinline__ void cp_wait0() {
    asm volatile("cp.async.wait_group 0;\n" ::: "memory");
}
__device__ __forceinline__ void ldsm_x4(uint32_t& r0, uint32_t& r1, uint32_t& r2, uint32_t& r3,
                                        uint32_t addr) {
    asm volatile("ldmatrix.sync.aligned.m8n8.x4.shared.b16 {%0,%1,%2,%3}, [%4];"
                 : "=r"(r0), "=r"(r1), "=r"(r2), "=r"(r3) : "r"(addr));
}
__device__ __forceinline__ void ldsm_x4t(uint32_t& r0, uint32_t& r1, uint32_t& r2, uint32_t& r3,
                                         uint32_t addr) {
    asm volatile("ldmatrix.sync.aligned.m8n8.x4.trans.shared.b16 {%0,%1,%2,%3}, [%4];"
                 : "=r"(r0), "=r"(r1), "=r"(r2), "=r"(r3) : "r"(addr));
}
__device__ __forceinline__ void mma16816(float* c,
                                         uint32_t a0, uint32_t a1, uint32_t a2, uint32_t a3,
                                         uint32_t b0, uint32_t b1) {
    asm volatile("mma.sync.aligned.m16n8k16.row.col.f32.f16.f16.f32 "
                 "{%0,%1,%2,%3}, {%4,%5,%6,%7}, {%8,%9}, {%0,%1,%2,%3};"
                 : "+f"(c[0]), "+f"(c[1]), "+f"(c[2]), "+f"(c[3])
                 : "r"(a0), "r"(a1), "r"(a2), "r"(a3), "r"(b0), "r"(b1));
}

// ---------------------------------------------------------------------------
// fp32 -> fp16 convert, vectorized by 4.
// ---------------------------------------------------------------------------
__global__ void __launch_bounds__(256) cvt_fp16(
    const float4* __restrict__ src, __half2* __restrict__ hi, int n4)
{
    const int i = blockIdx.x * blockDim.x + threadIdx.x;
    if (i >= n4) return;
    float4 v = src[i];
    hi[2*i]   = __halves2half2(__float2half_rn(v.x), __float2half_rn(v.y));
    hi[2*i+1] = __halves2half2(__float2half_rn(v.z), __float2half_rn(v.w));
}

// ---------------------------------------------------------------------------
// Plain fp16 tensor-core GEMM + bias, cp.async double-buffered, BK=32.
//   C = Ahi @ Bhi + bias
// OUT_HALF=1: write fp16 hi. Else fp32.
// Warp grid 4x2 (warp tile 32x64): measured-best.
// ---------------------------------------------------------------------------
#define BK    32
#define A_STR 40
#define B_STR 136
#define HG_ABUF (128 * A_STR)
#define HG_BBUF (BK * B_STR)
#define HG_STAGE (HG_ABUF + HG_BBUF)
#define HG_SMEM  (2 * HG_STAGE * 2)              // ~37.5 KB

template<bool OUT_HALF>
__global__ void __launch_bounds__(256, 2) hgemm(
    const __half* __restrict__ Ahi,
    const __half* __restrict__ Bhi,
    const float* __restrict__ bias, float* __restrict__ C,
    __half* __restrict__ Chi,
    int N, int K)
{
    extern __shared__ __align__(16) __half hsm[];

    const int t    = threadIdx.x;
    const int warp = t >> 5;
    const int lane = t & 31;
    const int wm   = (warp >> 1) * 32;    // 4 m-stripes
    const int wn   = (warp & 1) * 64;     // 2 n-stripes

    const size_t aG   = (size_t)blockIdx.y * 128 * K;
    const int    bCol = blockIdx.x * 128;

    const int g     = lane >> 3;
    const int lr    = lane & 7;
    const int aRowF = (g & 1) * 8 + lr;
    const int aColF = (g >> 1) * 8;
    const int bRowT = lane & 15;
    const int bNT   = (lane >> 4) * 8;

    float acc[2][8][4];
    #pragma unroll
    for (int mt = 0; mt < 2; mt++)
        #pragma unroll
        for (int nt = 0; nt < 8; nt++)
            #pragma unroll
            for (int i = 0; i < 4; i++) acc[mt][nt][i] = 0.0f;

    auto load_tile = [&](int s, int ko) {
        __half* base = hsm + s * HG_STAGE;
        __half* aH = base;
        __half* bH = base + HG_ABUF;
        #pragma unroll
        for (int it = 0; it < 2; it++) {
            const int u   = it * 256 + t;
            const int row = u >> 2;
            const int c   = (u & 3) * 8;
            cp16(smem_u32(aH + row * A_STR + c), Ahi + aG + (size_t)row * K + ko + c);
        }
        #pragma unroll
        for (int it = 0; it < 2; it++) {
            const int u   = it * 256 + t;
            const int row = u >> 4;
            const int c   = (u & 15) * 8;
            cp16(smem_u32(bH + row * B_STR + c), Bhi + (size_t)(ko + row) * N + bCol + c);
        }
        cp_commit();
    };

    load_tile(0, 0);
    cp_wait0();
    __syncthreads();

    const int nk = K / BK;
    int buf = 0;
    for (int kt = 0; kt < nk; kt++) {
        if (kt + 1 < nk) load_tile(buf ^ 1, (kt + 1) * BK);

        const __half* base = hsm + buf * HG_STAGE;
        const __half* aH = base;
        const __half* bH = base + HG_ABUF;

        #pragma unroll
        for (int ks = 0; ks < 2; ks++) {
            uint32_t af[2][4], bf[8][2];
            #pragma unroll
            for (int mt = 0; mt < 2; mt++) {
                const int row = wm + mt * 16 + aRowF;
                ldsm_x4(af[mt][0], af[mt][1], af[mt][2], af[mt][3],
                        smem_u32(aH + row * A_STR + ks * 16 + aColF));
            }
            #pragma unroll
            for (int p = 0; p < 4; p++) {
                ldsm_x4t(bf[2*p][0], bf[2*p][1], bf[2*p+1][0], bf[2*p+1][1],
                         smem_u32(bH + (ks * 16 + bRowT) * B_STR + wn + p * 16 + bNT));
            }
            #pragma unroll
            for (int mt = 0; mt < 2; mt++)
                #pragma unroll
                for (int nt = 0; nt < 8; nt++)
                    mma16816(acc[mt][nt], af[mt][0], af[mt][1], af[mt][2], af[mt][3],
                             bf[nt][0], bf[nt][1]);
        }

        if (kt + 1 < nk) {
            cp_wait0();
            __syncthreads();
            buf ^= 1;
        }
    }

    #pragma unroll
    for (int mt = 0; mt < 2; mt++) {
        const int r0 = blockIdx.y * 128 + wm + mt * 16 + (lane >> 2);
        #pragma unroll
        for (int nt = 0; nt < 8; nt++) {
            const int c0 = bCol + wn + nt * 8 + (lane & 3) * 2;
            const float b0 = bias[c0], b1 = bias[c0 + 1];
            const float v00 = acc[mt][nt][0] + b0, v01 = acc[mt][nt][1] + b1;
            const float v10 = acc[mt][nt][2] + b0, v11 = acc[mt][nt][3] + b1;
            if (OUT_HALF) {
                *(__half2*)(Chi + (size_t)r0 * N + c0) =
                    __halves2half2(__float2half_rn(v00), __float2half_rn(v01));
                *(__half2*)(Chi + (size_t)(r0 + 8) * N + c0) =
                    __halves2half2(__float2half_rn(v10), __float2half_rn(v11));
            } else {
                *(float2*)(C + (size_t)r0 * N + c0)       = make_float2(v00, v01);
                *(float2*)(C + (size_t)(r0 + 8) * N + c0) = make_float2(v10, v11);
            }
        }
    }
}

// ---------------------------------------------------------------------------
// Tensor-core flash attention, all-hi fp16 (unchanged from R16):
//   S = Qhi@Khi^T, P = exp2(S*qs - rl*dist), O = Phi@Vhi, y = O/l (hi fp16).
// 3 CTAs/SM. Window 14/r.
// ---------------------------------------------------------------------------
#define KV_STR 72
#define AT_BUF (64 * KV_STR)
#define AT_STAGE (2 * AT_BUF)                 // K hi, V hi
#define AT_SMEM ((AT_BUF + 2 * AT_STAGE) * 2)   // bytes (~45 KB)

__global__ void __launch_bounds__(128, 3) attn_mma(
    const __half* __restrict__ qkhi, const float* __restrict__ decay,
    __half* __restrict__ yhi)
{
    extern __shared__ __align__(16) __half asm_[];
    __half* QsH = asm_;

    const int q0   = blockIdx.x * 64;
    const int h    = blockIdx.y;
    const int bb   = blockIdx.z;
    const int t    = threadIdx.x;
    const int warp = t >> 5;
    const int lane = t & 31;

    const size_t rowBase = (size_t)bb * SEQ;
    const float r  = decay[h];
    const float rl = r * LOG2E;
    const float qs = 0.125f * LOG2E;

    {
        #pragma unroll
        for (int it = 0; it < 4; it++) {
            const int u = it * 128 + t;
            const int row = u >> 3;
            const int c = (u & 7) * 8;
            const size_t gsrc = (rowBase + q0 + row) * C3 + h * HD + c;
            cp16(smem_u32(QsH + row * KV_STR + c), qkhi + gsrc);
        }
        cp_commit();
    }

    auto load_kv = [&](int s, int k0) {
        __half* st = asm_ + AT_BUF + s * AT_STAGE;
        __half* kH = st;
        __half* vH = st + AT_BUF;
        #pragma unroll
        for (int it = 0; it < 4; it++) {
            const int u = it * 128 + t;
            const int row = u >> 3;
            const int c = (u & 7) * 8;
            const size_t gk = (rowBase + k0 + row) * C3 + CDIM + h * HD + c;
            cp16(smem_u32(kH + row * KV_STR + c), qkhi + gk);
            cp16(smem_u32(vH + row * KV_STR + c), qkhi + gk + CDIM);
        }
        cp_commit();
    };

    const int W = (r > 1e-6f) ? (int)(14.0f / r) : (1 << 30);
    int km = q0 - W;
    if (km < 0) km = 0;
    const int kstart = (km / 64) * 64;

    load_kv(0, kstart);
    cp_wait0();
    __syncthreads();

    const int lr   = lane & 7;
    const int aRow = lr + ((lane >> 3) & 1) * 8;
    const int aCol = (lane >> 4) * 8;
    const int kN   = ((lane >> 4) & 1) * 8;
    const int kK   = ((lane >> 3) & 1) * 8;
    const int vRow = lane & 15;
    const int vN   = (lane >> 4) * 8;

    uint32_t qh[4][4];
    #pragma unroll
    for (int ks = 0; ks < 4; ks++) {
        ldsm_x4(qh[ks][0], qh[ks][1], qh[ks][2], qh[ks][3],
                smem_u32(QsH + (warp * 16 + aRow) * KV_STR + ks * 16 + aCol));
    }

    float O[8][4];
    #pragma unroll
    for (int nt = 0; nt < 8; nt++)
        #pragma unroll
        for (int i = 0; i < 4; i++) O[nt][i] = 0.0f;
    float lsum0 = 0.0f, lsum1 = 0.0f;

    int buf = 0;
    for (int k0 = kstart; k0 <= q0; k0 += 64) {
        if (k0 != kstart) {
            cp_wait0();
            __syncthreads();
        }
        if (k0 + 64 <= q0) load_kv(buf ^ 1, k0 + 64);

        __half* st = asm_ + AT_BUF + buf * AT_STAGE;
        const __half* KsH = st;
        const __half* VsH = st + AT_BUF;

        float S[8][4];
        #pragma unroll
        for (int nt = 0; nt < 8; nt++)
            #pragma unroll
            for (int i = 0; i < 4; i++) S[nt][i] = 0.0f;

        #pragma unroll
        for (int ks = 0; ks < 4; ks++) {
            #pragma unroll
            for (int np = 0; np < 4; np++) {
                uint32_t b0, b1, b2, b3;
                ldsm_x4(b0, b1, b2, b3,
                        smem_u32(KsH + (np * 16 + kN + lr) * KV_STR + ks * 16 + kK));
                mma16816(S[2*np],   qh[ks][0], qh[ks][1], qh[ks][2], qh[ks][3], b0, b1);
                mma16816(S[2*np+1], qh[ks][0], qh[ks][1], qh[ks][2], qh[ks][3], b2, b3);
            }
        }

        // P = exp2(S*qs - rl*dist), causal; hi fp16
        uint32_t PH0[8], PH1[8];
        const float i0f = (float)(q0 + warp * 16 + (lane >> 2) - k0);
        const float i1f = i0f + 8.0f;
        const float jcb = (float)((lane & 3) * 2);
        #pragma unroll
        for (int nt = 0; nt < 8; nt++) {
            const float jc  = (float)(nt * 8) + jcb;
            const float d00 = i0f - jc, d01 = d00 - 1.0f;
            const float d10 = i1f - jc, d11 = d10 - 1.0f;
            const float p00 = (d00 >= 0.0f) ? ex2(fmaf(S[nt][0], qs, -rl * d00)) : 0.0f;
            const float p01 = (d01 >= 0.0f) ? ex2(fmaf(S[nt][1], qs, -rl * d01)) : 0.0f;
            const float p10 = (d10 >= 0.0f) ? ex2(fmaf(S[nt][2], qs, -rl * d10)) : 0.0f;
            const float p11 = (d11 >= 0.0f) ? ex2(fmaf(S[nt][3], qs, -rl * d11)) : 0.0f;
            lsum0 += p00 + p01;
            lsum1 += p10 + p11;
            __half2 hh0 = __halves2half2(__float2half_rn(p00), __float2half_rn(p01));
            __half2 hh1 = __halves2half2(__float2half_rn(p10), __float2half_rn(p11));
            PH0[nt] = *reinterpret_cast<uint32_t*>(&hh0);
            PH1[nt] = *reinterpret_cast<uint32_t*>(&hh1);
        }

        // O += Phi @ Vhi
        #pragma unroll
        for (int ks = 0; ks < 4; ks++) {
            const uint32_t a0 = PH0[2*ks], a1 = PH1[2*ks], a2 = PH0[2*ks+1], a3 = PH1[2*ks+1];
            #pragma unroll
            for (int np = 0; np < 4; np++) {
                uint32_t v0, v1, v2, v3;
                ldsm_x4t(v0, v1, v2, v3,
                         smem_u32(VsH + (ks * 16 + vRow) * KV_STR + np * 16 + vN));
                mma16816(O[2*np],   a0, a1, a2, a3, v0, v1);
                mma16816(O[2*np+1], a0, a1, a2, a3, v2, v3);
            }
        }
        buf ^= 1;
    }

    lsum0 += __shfl_xor_sync(0xffffffffu, lsum0, 1);
    lsum0 += __shfl_xor_sync(0xffffffffu, lsum0, 2);
    lsum1 += __shfl_xor_sync(0xffffffffu, lsum1, 1);
    lsum1 += __shfl_xor_sync(0xffffffffu, lsum1, 2);
    const float inv0 = 1.0f / lsum0;
    const float inv1 = 1.0f / lsum1;

    const int irow = q0 + warp * 16 + (lane >> 2);
    const size_t rb0 = (rowBase + irow) * CDIM + h * HD;
    const size_t rb1 = rb0 + (size_t)8 * CDIM;
    #pragma unroll
    for (int nt = 0; nt < 8; nt++) {
        const int col = nt * 8 + (lane & 3) * 2;
        *(__half2*)(yhi + rb0 + col) = __halves2half2(
            __float2half_rn(O[nt][0] * inv0), __float2half_rn(O[nt][1] * inv0));
        *(__half2*)(yhi + rb1 + col) = __halves2half2(
            __float2half_rn(O[nt][2] * inv1), __float2half_rn(O[nt][3] * inv1));
    }
}

// ---------------------------------------------------------------------------
extern "C" void kernel_launch(void* const* d_in, const int* in_sizes, int n_in,
                              void* d_out, int out_size)
{
    const float* x      = (const float*)d_in[0];
    const float* W_attn = (const float*)d_in[1];
    const float* b_attn = (const float*)d_in[2];
    const float* W_proj = (const float*)d_in[3];
    const float* b_proj = (const float*)d_in[4];
    const float* decay  = (const float*)d_in[5];
    float* out = (float*)d_out;

    __half *qkhi, *xhi, *wahi, *wphi, *yhi;
    cudaGetSymbolAddress((void**)&qkhi, g_qkhi);
    cudaGetSymbolAddress((void**)&xhi,  g_xhi);
    cudaGetSymbolAddress((void**)&wahi, g_wahi);
    cudaGetSymbolAddress((void**)&wphi, g_wphi);
    cudaGetSymbolAddress((void**)&yhi,  g_yhi);

    static bool attr_set = false;
    if (!attr_set) {
        cudaFuncSetAttribute((const void*)hgemm<true>,
                             cudaFuncAttributeMaxDynamicSharedMemorySize, HG_SMEM);
        cudaFuncSetAttribute((const void*)hgemm<false>,
                             cudaFuncAttributeMaxDynamicSharedMemorySize, HG_SMEM);
        cudaFuncSetAttribute((const void*)attn_mma,
                             cudaFuncAttributeMaxDynamicSharedMemorySize, AT_SMEM);
        attr_set = true;
    }

    // 0) fp16 converts (all hi-only now)
    {
        int n4 = MROWS * CDIM / 4;
        cvt_fp16<<<(n4 + 255) / 256, 256>>>((const float4*)x, (__half2*)xhi, n4);
        n4 = CDIM * C3 / 4;
        cvt_fp16<<<(n4 + 255) / 256, 256>>>((const float4*)W_attn, (__half2*)wahi, n4);
        n4 = CDIM * CDIM / 4;
        cvt_fp16<<<(n4 + 255) / 256, 256>>>((const float4*)W_proj, (__half2*)wphi, n4);
    }
    // 1) qkv = x @ W_attn + b_attn -> fp16 hi (plain hi GEMM)
    {
        dim3 grid(C3 / 128, MROWS / 128);
        hgemm<true><<<grid, 256, HG_SMEM>>>(xhi, wahi, b_attn, nullptr, qkhi, C3, CDIM);
    }
    // 2) fused decay attention -> yhi
    {
        dim3 grid(SEQ / 64, NHEAD, BATCH);
        attn_mma<<<grid, 128, AT_SMEM>>>(qkhi, decay, yhi);
    }
    // 3) out = y @ W_proj + b_proj -> fp32 (plain hi GEMM)
    {
        dim3 grid(CDIM / 128, MROWS / 128);
        hgemm<false><<<grid, 256, HG_SMEM>>>(yhi, wphi, b_proj, out, nullptr, CDIM, CDIM);
    }
}